// round 13
// baseline (speedup 1.0000x reference)
#include <cuda_runtime.h>
#include <cuda_bf16.h>
#include <cuda_fp16.h>
#include <math.h>
#include <stdint.h>

// ---------------- problem constants ----------------
constexpr int NT  = 50000;
constexpr int NC  = 10000;
constexpr int H   = 4;
constexpr int HID = 256;
constexpr int E_TT = 400000;
constexpr int E_CT = 200000;
constexpr int FT = 128;
constexpr int FC = 64;
constexpr int PW = 768;        // p1|p2|pd concat width
constexpr int NHALF = 25088;   // 128-aligned split of NT for tail pipelining

// ---------------- device scratch ----------------
__device__ float g_ht[NT * HID];               // fp32 ht for skip connection
__device__ __half g_p16[NT * PW];              // fp16 p (logits + gather)
__device__ __half g_ps16[NC * HID];
__device__ float g_as0[NT * H], g_ad0[NT * H];
__device__ float g_as1[NT * H], g_ad1[NT * H];
__device__ float g_as2[NC * H], g_ad2[NT * H];
// CSR scratch
__device__ int g_cnt[3 * NT];
__device__ int g_cur[3 * NT];
__device__ int g_rowp[3 * (NT + 1)];
__device__ int g_col0[E_TT];
__device__ int g_col1[E_TT];
__device__ int g_col2[E_CT];
// fp16 activations
__device__ __half g_xt16[NT * FT];
__device__ __half g_xc16[NC * FC];
__device__ __half g_ht16[NT * HID];
__device__ __half g_hc16[NC * HID];
__device__ __half g_xb16[NT * HID];
// fp16 hi/lo transposed weights [N, K]
__device__ __half g_wt_hi[HID * FT],  g_wt_lo[HID * FT];
__device__ __half g_wc_hi[HID * FC],  g_wc_lo[HID * FC];
__device__ __half g_w3_hi[PW * HID],  g_w3_lo[PW * HID];   // s2d|d2s|ct_dst
__device__ __half g_ws_hi[HID * HID], g_ws_lo[HID * HID];
__device__ __half g_wo_hi[HID * HID], g_wo_lo[HID * HID];

// ---------------- fused conversion kernels ----------------
__global__ void cvt_all_kernel(const float* __restrict__ xt, const float* __restrict__ xc,
                               __half* __restrict__ xt16, __half* __restrict__ xc16) {
    const int i4 = blockIdx.x * blockDim.x + threadIdx.x;
    constexpr int N1 = NT * FT / 4;
    constexpr int N2 = NC * FC / 4;
    if (i4 >= N1 + N2) return;
    const float* src;
    __half* dst;
    int i;
    if (i4 < N1) { src = xt; dst = xt16; i = i4 * 4; }
    else { src = xc; dst = xc16; i = (i4 - N1) * 4; }
    const float4 v = *reinterpret_cast<const float4*>(src + i);
    *reinterpret_cast<__half2*>(dst + i)     = __float22half2_rn(make_float2(v.x, v.y));
    *reinterpret_cast<__half2*>(dst + i + 2) = __float22half2_rn(make_float2(v.z, v.w));
}

__global__ void splitW_all_kernel(
        const float* __restrict__ Wt, const float* __restrict__ Wc,
        const float* __restrict__ Ws2d, const float* __restrict__ Wd2s,
        const float* __restrict__ Wctd, const float* __restrict__ Wcts,
        const float* __restrict__ Wout,
        __half* __restrict__ wt_hi, __half* __restrict__ wt_lo,
        __half* __restrict__ wc_hi, __half* __restrict__ wc_lo,
        __half* __restrict__ w3_hi, __half* __restrict__ w3_lo,
        __half* __restrict__ ws_hi, __half* __restrict__ ws_lo,
        __half* __restrict__ wo_hi, __half* __restrict__ wo_lo) {
    const int idx = blockIdx.x * blockDim.x + threadIdx.x;
    constexpr int S1 = FT * HID;
    constexpr int S2 = S1 + FC * HID;
    constexpr int S3 = S2 + HID * HID;
    constexpr int S4 = S3 + HID * HID;
    constexpr int S5 = S4 + HID * HID;
    constexpr int S6 = S5 + HID * HID;
    constexpr int S7 = S6 + HID * HID;
    if (idx >= S7) return;
    const float* W; __half *hi, *lo; int K, local, nOff = 0;
    if (idx < S1)      { W = Wt;   hi = wt_hi; lo = wt_lo; K = FT;  local = idx; }
    else if (idx < S2) { W = Wc;   hi = wc_hi; lo = wc_lo; K = FC;  local = idx - S1; }
    else if (idx < S3) { W = Ws2d; hi = w3_hi; lo = w3_lo; K = HID; local = idx - S2; }
    else if (idx < S4) { W = Wd2s; hi = w3_hi; lo = w3_lo; K = HID; local = idx - S3; nOff = 256; }
    else if (idx < S5) { W = Wctd; hi = w3_hi; lo = w3_lo; K = HID; local = idx - S4; nOff = 512; }
    else if (idx < S6) { W = Wcts; hi = ws_hi; lo = ws_lo; K = HID; local = idx - S5; }
    else               { W = Wout; hi = wo_hi; lo = wo_lo; K = HID; local = idx - S6; }
    const int k = local >> 8;
    const int n = local & 255;
    const float v = W[local];
    const __half h = __float2half_rn(v);
    const __half l = __float2half_rn(v - __half2float(h));
    hi[(size_t)(nOff + n) * K + k] = h;
    lo[(size_t)(nOff + n) * K + k] = l;
}

// ---------------- CSR build ----------------
__global__ void count_kernel(const int* __restrict__ tt_src, const int* __restrict__ tt_dst,
                             const int* __restrict__ ct_dst, int* __restrict__ cnt) {
    const int e = blockIdx.x * blockDim.x + threadIdx.x;
    if (e < E_TT) {
        atomicAdd(&cnt[tt_dst[e]], 1);
        atomicAdd(&cnt[NT + tt_src[e]], 1);
    }
    if (e < E_CT) atomicAdd(&cnt[2 * NT + ct_dst[e]], 1);
}

__global__ void __launch_bounds__(1024) scan3_kernel(
        const int* __restrict__ cnt, int* __restrict__ rowp, int* __restrict__ cur) {
    const int a = blockIdx.x;
    const int* c = cnt + a * NT;
    int* rp = rowp + a * (NT + 1);
    int* cu = cur + a * NT;
    __shared__ int warp_tot[32];
    __shared__ int s_carry;
    const int tid = threadIdx.x;
    const int lane = tid & 31, wid = tid >> 5;
    if (tid == 0) s_carry = 0;
    __syncthreads();
    for (int base = 0; base < NT; base += 1024) {
        const int i = base + tid;
        const int v = (i < NT) ? c[i] : 0;
        int x = v;
#pragma unroll
        for (int o = 1; o < 32; o <<= 1) {
            const int y = __shfl_up_sync(~0u, x, o);
            if (lane >= o) x += y;
        }
        if (lane == 31) warp_tot[wid] = x;
        __syncthreads();
        if (wid == 0) {
            int t = warp_tot[lane];
#pragma unroll
            for (int o = 1; o < 32; o <<= 1) {
                const int y = __shfl_up_sync(~0u, t, o);
                if (lane >= o) t += y;
            }
            warp_tot[lane] = t;
        }
        __syncthreads();
        const int carry = s_carry;
        const int woff = (wid > 0) ? warp_tot[wid - 1] : 0;
        const int excl = carry + woff + (x - v);
        if (i < NT) { rp[i] = excl; cu[i] = excl; }
        __syncthreads();
        if (tid == 0) s_carry = carry + warp_tot[31];
        __syncthreads();
    }
    if (tid == 0) rp[NT] = s_carry;
}

__global__ void scatter_kernel(const int* __restrict__ tt_src, const int* __restrict__ tt_dst,
                               const int* __restrict__ ct_src, const int* __restrict__ ct_dst,
                               int* __restrict__ cur,
                               int* __restrict__ col0, int* __restrict__ col1,
                               int* __restrict__ col2) {
    const int e = blockIdx.x * blockDim.x + threadIdx.x;
    if (e < E_TT) {
        const int s = tt_src[e], d = tt_dst[e];
        col0[atomicAdd(&cur[d], 1)] = s;
        col1[atomicAdd(&cur[NT + s], 1)] = d;
    }
    if (e < E_CT) {
        col2[atomicAdd(&cur[2 * NT + ct_dst[e]], 1)] = ct_src[e];
    }
}

// ================= fp16 asymmetric-split tensor-core GEMM (ldmatrix) ========
constexpr int SA = 40;
constexpr int TILE_ARR = 128 * SA;
constexpr int OFF_A   = 0;
constexpr int OFF_BHI = TILE_ARR;
constexpr int OFF_BLO = 2 * TILE_ARR;
constexpr int BUF_STRIDE = 3 * TILE_ARR;
constexpr int GEMM_SMEM = 2 * BUF_STRIDE * 2; // bytes = 61440

__device__ __forceinline__ void cpa16(__half* smem, const __half* gmem) {
    uint32_t sa = (uint32_t)__cvta_generic_to_shared(smem);
    asm volatile("cp.async.ca.shared.global [%0], [%1], 16;" :: "r"(sa), "l"(gmem));
}

__device__ __forceinline__ void mma16816h(float* c, const uint32_t* a, const uint32_t* b) {
    asm volatile(
        "mma.sync.aligned.m16n8k16.row.col.f32.f16.f16.f32 "
        "{%0,%1,%2,%3}, {%4,%5,%6,%7}, {%8,%9}, {%0,%1,%2,%3};"
        : "+f"(c[0]), "+f"(c[1]), "+f"(c[2]), "+f"(c[3])
        : "r"(a[0]), "r"(a[1]), "r"(a[2]), "r"(a[3]), "r"(b[0]), "r"(b[1]));
}

__device__ __forceinline__ void ldsm4(uint32_t& r0, uint32_t& r1, uint32_t& r2,
                                      uint32_t& r3, uint32_t addr) {
    asm volatile("ldmatrix.sync.aligned.m8n8.x4.shared.b16 {%0,%1,%2,%3}, [%4];"
                 : "=r"(r0), "=r"(r1), "=r"(r2), "=r"(r3) : "r"(addr));
}

template <bool BIAS, bool RELU, bool WF32, bool WF16>
__global__ void __launch_bounds__(512, 2) mma_gemm3(
        const __half* __restrict__ A,
        const __half* __restrict__ Bhi, const __half* __restrict__ Blo,
        const float* __restrict__ bias,
        float* __restrict__ Cf32, __half* __restrict__ C16,
        int M, int N, int K) {
    extern __shared__ __align__(16) char dynsmem[];
    __half* sm = reinterpret_cast<__half*>(dynsmem);
    const uint32_t sb = (uint32_t)__cvta_generic_to_shared(sm);

    const int tid = threadIdx.x;
    const int bm = blockIdx.y * 128;
    const int bn = blockIdx.x * 128;
    const int wid = tid >> 5;
    const int lane = tid & 31;
    const int wm = wid >> 2;
    const int wn = wid & 3;
    const int g = lane >> 2;
    const int t = lane & 3;

    const int frow = tid >> 2;
    const int fkc  = (tid & 3) * 8;
    int garow = bm + frow; if (garow >= M) garow = M - 1;
    const int gbrow = bn + frow;

    const int aRow = wm * 32 + (lane & 7) + ((lane >> 3) & 1) * 8;
    const int aK   = ((lane >> 4) & 1) * 8;
    const int bRow = wn * 32 + (lane & 7) + ((lane >> 4) & 1) * 8;
    const int bK   = ((lane >> 3) & 1) * 8;
    const uint32_t aOff  = (uint32_t)(OFF_A   + aRow * SA + aK) * 2;
    const uint32_t bhOff = (uint32_t)(OFF_BHI + bRow * SA + bK) * 2;
    const uint32_t blOff = (uint32_t)(OFF_BLO + bRow * SA + bK) * 2;

    float acc[2][4][4];
#pragma unroll
    for (int mi = 0; mi < 2; mi++)
#pragma unroll
        for (int ni = 0; ni < 4; ni++)
#pragma unroll
            for (int r = 0; r < 4; r++) acc[mi][ni][r] = 0.f;

    const int KT = K >> 5;
    {
        const size_t ao = (size_t)garow * K + fkc;
        const size_t bo = (size_t)gbrow * K + fkc;
        __half* b0 = sm;
        cpa16(b0 + OFF_A   + frow * SA + fkc, A + ao);
        cpa16(b0 + OFF_BHI + frow * SA + fkc, Bhi + bo);
        cpa16(b0 + OFF_BLO + frow * SA + fkc, Blo + bo);
        asm volatile("cp.async.commit_group;");
    }

    for (int kt = 0; kt < KT; kt++) {
        asm volatile("cp.async.wait_group 0;");
        __syncthreads();
        if (kt + 1 < KT) {
            const int k0 = (kt + 1) << 5;
            const size_t ao = (size_t)garow * K + k0 + fkc;
            const size_t bo = (size_t)gbrow * K + k0 + fkc;
            __half* nb = sm + ((kt + 1) & 1) * BUF_STRIDE;
            cpa16(nb + OFF_A   + frow * SA + fkc, A + ao);
            cpa16(nb + OFF_BHI + frow * SA + fkc, Bhi + bo);
            cpa16(nb + OFF_BLO + frow * SA + fkc, Blo + bo);
            asm volatile("cp.async.commit_group;");
        }
        const uint32_t bufb = sb + ((kt & 1) * BUF_STRIDE) * 2;

#pragma unroll
        for (int ks = 0; ks < 2; ks++) {
            const uint32_t kByte = (uint32_t)(ks * 16) * 2;
            uint32_t bh[4][2], bl[4][2];
            const uint32_t bhAddr = bufb + bhOff + kByte;
            const uint32_t blAddr = bufb + blOff + kByte;
            ldsm4(bh[0][0], bh[0][1], bh[1][0], bh[1][1], bhAddr);
            ldsm4(bh[2][0], bh[2][1], bh[3][0], bh[3][1], bhAddr + 16 * SA * 2);
            ldsm4(bl[0][0], bl[0][1], bl[1][0], bl[1][1], blAddr);
            ldsm4(bl[2][0], bl[2][1], bl[3][0], bl[3][1], blAddr + 16 * SA * 2);
            const uint32_t aAddr0 = bufb + aOff + kByte;
#pragma unroll
            for (int mi = 0; mi < 2; mi++) {
                uint32_t a[4];
                ldsm4(a[0], a[1], a[2], a[3], aAddr0 + (uint32_t)(mi * 16 * SA) * 2);
#pragma unroll
                for (int ni = 0; ni < 4; ni++) {
                    mma16816h(acc[mi][ni], a, bh[ni]);
                    mma16816h(acc[mi][ni], a, bl[ni]);
                }
            }
        }
    }

#pragma unroll
    for (int mi = 0; mi < 2; mi++) {
        const int row0 = bm + wm * 32 + mi * 16 + g;
#pragma unroll
        for (int ni = 0; ni < 4; ni++) {
            const int col = bn + wn * 32 + ni * 8 + 2 * t;
            float c0 = acc[mi][ni][0], c1 = acc[mi][ni][1];
            float c2 = acc[mi][ni][2], c3 = acc[mi][ni][3];
            if (BIAS) {
                const float b0 = bias[col], b1 = bias[col + 1];
                c0 += b0; c1 += b1; c2 += b0; c3 += b1;
            }
            if (RELU) {
                c0 = fmaxf(c0, 0.f); c1 = fmaxf(c1, 0.f);
                c2 = fmaxf(c2, 0.f); c3 = fmaxf(c3, 0.f);
            }
#pragma unroll
            for (int rr = 0; rr < 2; rr++) {
                const int row = row0 + rr * 8;
                if (row >= M) continue;
                const float v0 = rr ? c2 : c0;
                const float v1 = rr ? c3 : c1;
                const size_t off = (size_t)row * N + col;
                if (WF32)
                    *reinterpret_cast<float2*>(Cf32 + off) = make_float2(v0, v1);
                if (WF16)
                    *reinterpret_cast<__half2*>(C16 + off) =
                        __float22half2_rn(make_float2(v0, v1));
            }
        }
    }
}

// ---------------- alpha kernels (fp16 p reads) ----------------
__global__ void alpha_kernel(const __half* __restrict__ p, int stride,
                             const float* __restrict__ att,
                             float* __restrict__ out, int N) {
    const int gw = (blockIdx.x * blockDim.x + threadIdx.x) >> 5;
    const int lane = threadIdx.x & 31;
    if (gw >= N * H) return;
    const int n = gw >> 2;
    const int h = gw & 3;
    const __half* pr = p + (size_t)n * stride + h * 64;
    const float* at = att + h * 64;
    float s = __half2float(pr[lane]) * at[lane] +
              __half2float(pr[lane + 32]) * at[lane + 32];
#pragma unroll
    for (int o = 16; o > 0; o >>= 1) s += __shfl_xor_sync(0xffffffffu, s, o);
    if (lane == 0) out[gw] = s;
}

__global__ void alpha5_kernel(const __half* __restrict__ p,
                              const float* __restrict__ a_s0, const float* __restrict__ a_d0,
                              const float* __restrict__ a_s1, const float* __restrict__ a_d1,
                              const float* __restrict__ a_d2,
                              float* __restrict__ as0, float* __restrict__ ad0,
                              float* __restrict__ as1, float* __restrict__ ad1,
                              float* __restrict__ ad2) {
    const int gw = (blockIdx.x * blockDim.x + threadIdx.x) >> 5;
    const int lane = threadIdx.x & 31;
    if (gw >= NT * H) return;
    const int n = gw >> 2;
    const int h = gw & 3;
    const __half* r1 = p + (size_t)n * PW + h * 64;
    const __half* r2 = r1 + 256;
    const __half* r3 = r1 + 512;
    const float x1a = __half2float(r1[lane]), x1b = __half2float(r1[lane + 32]);
    const float x2a = __half2float(r2[lane]), x2b = __half2float(r2[lane + 32]);
    const float x3a = __half2float(r3[lane]), x3b = __half2float(r3[lane + 32]);
    const float* v;
    v = a_s0 + h * 64; float s0 = x1a * v[lane] + x1b * v[lane + 32];
    v = a_d0 + h * 64; float s1 = x1a * v[lane] + x1b * v[lane + 32];
    v = a_s1 + h * 64; float s2 = x2a * v[lane] + x2b * v[lane + 32];
    v = a_d1 + h * 64; float s3 = x2a * v[lane] + x2b * v[lane + 32];
    v = a_d2 + h * 64; float s4 = x3a * v[lane] + x3b * v[lane + 32];
#pragma unroll
    for (int o = 16; o > 0; o >>= 1) {
        s0 += __shfl_xor_sync(0xffffffffu, s0, o);
        s1 += __shfl_xor_sync(0xffffffffu, s1, o);
        s2 += __shfl_xor_sync(0xffffffffu, s2, o);
        s3 += __shfl_xor_sync(0xffffffffu, s3, o);
        s4 += __shfl_xor_sync(0xffffffffu, s4, o);
    }
    if (lane == 0) { as0[gw] = s0; ad0[gw] = s1; as1[gw] = s2; ad1[gw] = s3; ad2[gw] = s4; }
}

// ---------------- fused CSR gather + combine ----------------
__device__ __forceinline__ void acc8_raw(float* acc, float ex, uint4 raw) {
    const __half2* hp = reinterpret_cast<const __half2*>(&raw);
    const float2 f0 = __half22float2(hp[0]);
    const float2 f1 = __half22float2(hp[1]);
    const float2 f2 = __half22float2(hp[2]);
    const float2 f3 = __half22float2(hp[3]);
    acc[0] += ex * f0.x; acc[1] += ex * f0.y;
    acc[2] += ex * f1.x; acc[3] += ex * f1.y;
    acc[4] += ex * f2.x; acc[5] += ex * f2.y;
    acc[6] += ex * f3.x; acc[7] += ex * f3.y;
}
__device__ __forceinline__ float lrelu_exp(float a) {
    a = a > 0.f ? a : 0.2f * a;
    return __expf(a);
}

template <int STRIDE>
__device__ __forceinline__ void gat_pass(
        const int* __restrict__ col, int e0, int e1,
        const float* __restrict__ asrc, float adn, int h,
        const __half* __restrict__ xbase, int k,
        float* acc, float& den) {
    int e = e0;
    for (; e + 4 <= e1; e += 4) {
        const int s0 = __ldg(col + e);
        const int s1 = __ldg(col + e + 1);
        const int s2 = __ldg(col + e + 2);
        const int s3 = __ldg(col + e + 3);
        const float l0 = __ldg(asrc + s0 * 4 + h);
        const float l1 = __ldg(asrc + s1 * 4 + h);
        const float l2 = __ldg(asrc + s2 * 4 + h);
        const float l3 = __ldg(asrc + s3 * 4 + h);
        const uint4 r0 = *reinterpret_cast<const uint4*>(xbase + (size_t)s0 * STRIDE + k);
        const uint4 r1 = *reinterpret_cast<const uint4*>(xbase + (size_t)s1 * STRIDE + k);
        const uint4 r2 = *reinterpret_cast<const uint4*>(xbase + (size_t)s2 * STRIDE + k);
        const uint4 r3 = *reinterpret_cast<const uint4*>(xbase + (size_t)s3 * STRIDE + k);
        const float e0x = lrelu_exp(l0 + adn);
        const float e1x = lrelu_exp(l1 + adn);
        const float e2x = lrelu_exp(l2 + adn);
        const float e3x = lrelu_exp(l3 + adn);
        den += (e0x + e1x) + (e2x + e3x);
        acc8_raw(acc, e0x, r0);
        acc8_raw(acc, e1x, r1);
        acc8_raw(acc, e2x, r2);
        acc8_raw(acc, e3x, r3);
    }
    for (; e < e1; e++) {
        const int s = __ldg(col + e);
        const float ex = lrelu_exp(__ldg(asrc + s * 4 + h) + adn);
        const uint4 r = *reinterpret_cast<const uint4*>(xbase + (size_t)s * STRIDE + k);
        den += ex;
        acc8_raw(acc, ex, r);
    }
}

__global__ void __launch_bounds__(256) gat_gather(
        const int* __restrict__ rowp,
        const int* __restrict__ col0, const int* __restrict__ col1,
        const int* __restrict__ col2,
        const float* __restrict__ as0, const float* __restrict__ ad0,
        const float* __restrict__ as1, const float* __restrict__ ad1,
        const float* __restrict__ as2, const float* __restrict__ ad2,
        const __half* __restrict__ p16, const __half* __restrict__ ps16,
        const float* __restrict__ ht,
        const float* __restrict__ b1, const float* __restrict__ b2,
        const float* __restrict__ b3,
        __half* __restrict__ xb16, int n0, int n1) {
    const int n = n0 + ((blockIdx.x * blockDim.x + threadIdx.x) >> 5);
    if (n >= n1) return;
    const int lane = threadIdx.x & 31;
    const int h = lane >> 3;
    const int k = lane * 8;

    const int* rp0 = rowp;
    const int* rp1 = rowp + (NT + 1);
    const int* rp2 = rowp + 2 * (NT + 1);

    float xacc[8];
    float acc[8];

    {
#pragma unroll
        for (int j = 0; j < 8; j++) acc[j] = 0.f;
        float den = 0.f;
        const float adn = ad0[n * 4 + h];
        gat_pass<PW>(col0, rp0[n], rp0[n + 1], as0, adn, h, p16, k, acc, den);
        {
            const float ex = lrelu_exp(as0[n * 4 + h] + adn);
            const uint4 r = *reinterpret_cast<const uint4*>(p16 + (size_t)n * PW + k);
            den += ex;
            acc8_raw(acc, ex, r);
        }
        const float r = 0.25f / fmaxf(den, 1e-16f);
#pragma unroll
        for (int j = 0; j < 8; j++) xacc[j] = r * acc[j];
    }

    {
#pragma unroll
        for (int j = 0; j < 8; j++) acc[j] = 0.f;
        float den = 0.f;
        const float adn = ad1[n * 4 + h];
        gat_pass<PW>(col1, rp1[n], rp1[n + 1], as1, adn, h, p16 + 256, k, acc, den);
        {
            const float ex = lrelu_exp(as1[n * 4 + h] + adn);
            const uint4 r = *reinterpret_cast<const uint4*>(p16 + (size_t)n * PW + 256 + k);
            den += ex;
            acc8_raw(acc, ex, r);
        }
        const float r = 0.25f / fmaxf(den, 1e-16f);
#pragma unroll
        for (int j = 0; j < 8; j++) xacc[j] += r * acc[j];
    }

    {
#pragma unroll
        for (int j = 0; j < 8; j++) acc[j] = 0.f;
        float den = 0.f;
        const float adn = ad2[n * 4 + h];
        gat_pass<HID>(col2, rp2[n], rp2[n + 1], as2, adn, h, ps16, k, acc, den);
        const float r = 0.5f / fmaxf(den, 1e-16f);
#pragma unroll
        for (int j = 0; j < 8; j++) xacc[j] += r * acc[j];
    }

    const float4 b1a = *reinterpret_cast<const float4*>(b1 + k);
    const float4 b1b = *reinterpret_cast<const float4*>(b1 + k + 4);
    const float4 b2a = *reinterpret_cast<const float4*>(b2 + k);
    const float4 b2b = *reinterpret_cast<const float4*>(b2 + k + 4);
    const float4 b3a = *reinterpret_cast<const float4*>(b3 + k);
    const float4 b3b = *reinterpret_cast<const float4*>(b3 + k + 4);
    const float4 h0 = *reinterpret_cast<const float4*>(ht + (size_t)n * HID + k);
    const float4 h1 = *reinterpret_cast<const float4*>(ht + (size_t)n * HID + k + 4);
    float xv[8];
    xv[0] = xacc[0] + 0.25f * (b1a.x + b2a.x) + 0.5f * b3a.x + h0.x;
    xv[1] = xacc[1] + 0.25f * (b1a.y + b2a.y) + 0.5f * b3a.y + h0.y;
    xv[2] = xacc[2] + 0.25f * (b1a.z + b2a.z) + 0.5f * b3a.z + h0.z;
    xv[3] = xacc[3] + 0.25f * (b1a.w + b2a.w) + 0.5f * b3a.w + h0.w;
    xv[4] = xacc[4] + 0.25f * (b1b.x + b2b.x) + 0.5f * b3b.x + h1.x;
    xv[5] = xacc[5] + 0.25f * (b1b.y + b2b.y) + 0.5f * b3b.y + h1.y;
    xv[6] = xacc[6] + 0.25f * (b1b.z + b2b.z) + 0.5f * b3b.z + h1.z;
    xv[7] = xacc[7] + 0.25f * (b1b.w + b2b.w) + 0.5f * b3b.w + h1.w;
    uint4 u;
    __half2* up = reinterpret_cast<__half2*>(&u);
#pragma unroll
    for (int j = 0; j < 4; j++) {
        const float a = fmaxf(xv[2 * j], 0.f);
        const float b = fmaxf(xv[2 * j + 1], 0.f);
        up[j] = __float22half2_rn(make_float2(a, b));
    }
    *reinterpret_cast<uint4*>(xb16 + (size_t)n * HID + k) = u;
}

// ---------------- launch ----------------
extern "C" void kernel_launch(void* const* d_in, const int* in_sizes, int n_in,
                              void* d_out, int out_size) {
    const float* x_target = (const float*)d_in[0];
    const float* x_context = (const float*)d_in[1];
    const int*   ei_tt     = (const int*)d_in[2];
    const int*   ei_ct_src = (const int*)d_in[3];
    const int*   ei_ct_dst = (const int*)d_in[4];
    const float* Wt = (const float*)d_in[5];
    const float* bt = (const float*)d_in[6];
    const float* Wc = (const float*)d_in[7];
    const float* bc = (const float*)d_in[8];
    const float* W_s2d  = (const float*)d_in[9];
    const float* as_s2d = (const float*)d_in[10];
    const float* ad_s2d = (const float*)d_in[11];
    const float* b_s2d  = (const float*)d_in[12];
    const float* W_d2s  = (const float*)d_in[13];
    const float* as_d2s = (const float*)d_in[14];
    const float* ad_d2s = (const float*)d_in[15];
    const float* b_d2s  = (const float*)d_in[16];
    const float* W_ct_src = (const float*)d_in[17];
    const float* W_ct_dst = (const float*)d_in[18];
    const float* as_ct  = (const float*)d_in[19];
    const float* ad_ct  = (const float*)d_in[20];
    const float* b_ct   = (const float*)d_in[21];
    const float* W_out  = (const float*)d_in[22];
    const float* b_out  = (const float*)d_in[23];

    float *ht, *as0, *ad0, *as1, *ad1, *as2, *ad2;
    cudaGetSymbolAddress((void**)&ht,  g_ht);
    cudaGetSymbolAddress((void**)&as0, g_as0);
    cudaGetSymbolAddress((void**)&ad0, g_ad0);
    cudaGetSymbolAddress((void**)&as1, g_as1);
    cudaGetSymbolAddress((void**)&ad1, g_ad1);
    cudaGetSymbolAddress((void**)&as2, g_as2);
    cudaGetSymbolAddress((void**)&ad2, g_ad2);

    __half *p16, *ps16, *xt16, *xc16, *ht16, *hc16, *xb16;
    cudaGetSymbolAddress((void**)&p16,  g_p16);
    cudaGetSymbolAddress((void**)&ps16, g_ps16);
    cudaGetSymbolAddress((void**)&xt16, g_xt16);
    cudaGetSymbolAddress((void**)&xc16, g_xc16);
    cudaGetSymbolAddress((void**)&ht16, g_ht16);
    cudaGetSymbolAddress((void**)&hc16, g_hc16);
    cudaGetSymbolAddress((void**)&xb16, g_xb16);

    int *cnt, *cur, *rowp, *col0, *col1, *col2;
    cudaGetSymbolAddress((void**)&cnt,  g_cnt);
    cudaGetSymbolAddress((void**)&cur,  g_cur);
    cudaGetSymbolAddress((void**)&rowp, g_rowp);
    cudaGetSymbolAddress((void**)&col0, g_col0);
    cudaGetSymbolAddress((void**)&col1, g_col1);
    cudaGetSymbolAddress((void**)&col2, g_col2);

    __half *wt_hi, *wt_lo, *wc_hi, *wc_lo, *w3_hi, *w3_lo, *ws_hi, *ws_lo, *wo_hi, *wo_lo;
    cudaGetSymbolAddress((void**)&wt_hi, g_wt_hi); cudaGetSymbolAddress((void**)&wt_lo, g_wt_lo);
    cudaGetSymbolAddress((void**)&wc_hi, g_wc_hi); cudaGetSymbolAddress((void**)&wc_lo, g_wc_lo);
    cudaGetSymbolAddress((void**)&w3_hi, g_w3_hi); cudaGetSymbolAddress((void**)&w3_lo, g_w3_lo);
    cudaGetSymbolAddress((void**)&ws_hi, g_ws_hi); cudaGetSymbolAddress((void**)&ws_lo, g_ws_lo);
    cudaGetSymbolAddress((void**)&wo_hi, g_wo_hi); cudaGetSymbolAddress((void**)&wo_lo, g_wo_lo);

    // one-time setup (first call is the uncaptured correctness run)
    static cudaStream_t s1 = nullptr, s2 = nullptr;
    static cudaEvent_t eFork = nullptr, eConv = nullptr, eS1 = nullptr, eS2 = nullptr;
    static cudaEvent_t eG0 = nullptr, eOut0 = nullptr;
    static bool init_done = false;
    if (!init_done) {
        cudaFuncSetAttribute(mma_gemm3<true, true, true, true>,
                             cudaFuncAttributeMaxDynamicSharedMemorySize, GEMM_SMEM);
        cudaFuncSetAttribute(mma_gemm3<true, true, false, true>,
                             cudaFuncAttributeMaxDynamicSharedMemorySize, GEMM_SMEM);
        cudaFuncSetAttribute(mma_gemm3<false, false, false, true>,
                             cudaFuncAttributeMaxDynamicSharedMemorySize, GEMM_SMEM);
        cudaFuncSetAttribute(mma_gemm3<true, false, true, false>,
                             cudaFuncAttributeMaxDynamicSharedMemorySize, GEMM_SMEM);
        cudaStreamCreateWithFlags(&s1, cudaStreamNonBlocking);
        cudaStreamCreateWithFlags(&s2, cudaStreamNonBlocking);
        cudaEventCreateWithFlags(&eFork, cudaEventDisableTiming);
        cudaEventCreateWithFlags(&eConv, cudaEventDisableTiming);
        cudaEventCreateWithFlags(&eS1, cudaEventDisableTiming);
        cudaEventCreateWithFlags(&eS2, cudaEventDisableTiming);
        cudaEventCreateWithFlags(&eG0, cudaEventDisableTiming);
        cudaEventCreateWithFlags(&eOut0, cudaEventDisableTiming);
        init_done = true;
    }

    const int* tt_src = ei_tt;
    const int* tt_dst = ei_tt + E_TT;

    const dim3 blk(512);
    const dim3 g_ht_g(HID / 128, (NT + 127) / 128);
    const dim3 g_hc_g(HID / 128, (NC + 127) / 128);
    const dim3 g_p_g(PW / 128, (NT + 127) / 128);
    const dim3 g_out0(HID / 128, NHALF / 128);                     // rows [0, NHALF)
    const dim3 g_out1(HID / 128, (NT - NHALF + 127) / 128);        // rows [NHALF, NT)

    // ---- fork point ----
    cudaEventRecord(eFork, 0);
    cudaStreamWaitEvent(s1, eFork, 0);
    cudaStreamWaitEvent(s2, eFork, 0);

    // ---- stream s2: CSR build (independent of everything else) ----
    cudaMemsetAsync(cnt, 0, sizeof(int) * 3 * NT, s2);
    count_kernel<<<(E_TT + 255) / 256, 256, 0, s2>>>(tt_src, tt_dst, ei_ct_dst, cnt);
    scan3_kernel<<<3, 1024, 0, s2>>>(cnt, rowp, cur);
    scatter_kernel<<<(E_TT + 255) / 256, 256, 0, s2>>>(tt_src, tt_dst, ei_ct_src,
                                                       ei_ct_dst, cur, col0, col1, col2);
    cudaEventRecord(eS2, s2);

    // ---- stream 0: conversions ----
    {
        const int ncvt = (NT * FT + NC * FC) / 4;
        cvt_all_kernel<<<(ncvt + 255) / 256, 256>>>(x_target, x_context, xt16, xc16);
    }
    splitW_all_kernel<<<(376832 + 255) / 256, 256>>>(
        Wt, Wc, W_s2d, W_d2s, W_ct_dst, W_ct_src, W_out,
        wt_hi, wt_lo, wc_hi, wc_lo, w3_hi, w3_lo, ws_hi, ws_lo, wo_hi, wo_lo);
    cudaEventRecord(eConv, 0);

    // ---- stream s1: small context chain (hc -> ps -> alpha(ps)) ----
    cudaStreamWaitEvent(s1, eConv, 0);
    mma_gemm3<true, true, false, true><<<g_hc_g, blk, GEMM_SMEM, s1>>>(
        xc16, wc_hi, wc_lo, bc, nullptr, hc16, NC, HID, FC);
    mma_gemm3<false, false, false, true><<<g_hc_g, blk, GEMM_SMEM, s1>>>(
        hc16, ws_hi, ws_lo, nullptr, nullptr, ps16, NC, HID, HID);
    alpha_kernel<<<(NC * H * 32 + 255) / 256, 256, 0, s1>>>(ps16, HID, as_ct, as2, NC);
    cudaEventRecord(eS1, s1);

    // ---- stream 0: big target chain ----
    mma_gemm3<true, true, true, true><<<g_ht_g, blk, GEMM_SMEM>>>(
        xt16, wt_hi, wt_lo, bt, ht, ht16, NT, HID, FT);
    mma_gemm3<false, false, false, true><<<g_p_g, blk, GEMM_SMEM>>>(
        ht16, w3_hi, w3_lo, nullptr, nullptr, p16, NT, PW, HID);
    alpha5_kernel<<<(NT * H * 32 + 255) / 256, 256>>>(
        p16, as_s2d, ad_s2d, as_d2s, ad_d2s, ad_ct, as0, ad0, as1, ad1, ad2);

    // ---- join for gather ----
    cudaStreamWaitEvent(0, eS1, 0);
    cudaStreamWaitEvent(0, eS2, 0);

    // ---- pipelined tail: gather/out in two row halves ----
    gat_gather<<<(NHALF * 32 + 255) / 256, 256>>>(
        rowp, col0, col1, col2, as0, ad0, as1, ad1, as2, ad2,
        p16, ps16, ht, b_s2d, b_d2s, b_ct, xb16, 0, NHALF);
    cudaEventRecord(eG0, 0);

    // s1: out-GEMM for half0, overlapping gather of half1
    cudaStreamWaitEvent(s1, eG0, 0);
    mma_gemm3<true, false, true, false><<<g_out0, blk, GEMM_SMEM, s1>>>(
        xb16, wo_hi, wo_lo, b_out, (float*)d_out, nullptr, NHALF, HID, HID);
    cudaEventRecord(eOut0, s1);

    // stream 0: gather half1, then out-GEMM half1
    gat_gather<<<((NT - NHALF) * 32 + 255) / 256, 256>>>(
        rowp, col0, col1, col2, as0, ad0, as1, ad1, as2, ad2,
        p16, ps16, ht, b_s2d, b_d2s, b_ct, xb16, NHALF, NT);
    mma_gemm3<true, false, true, false><<<g_out1, blk, GEMM_SMEM>>>(
        xb16 + (size_t)NHALF * HID, wo_hi, wo_lo, b_out,
        (float*)d_out + (size_t)NHALF * HID, nullptr, NT - NHALF, HID, HID);

    // final join
    cudaStreamWaitEvent(0, eOut0, 0);
}

// round 14
// speedup vs baseline: 1.1337x; 1.1337x over previous
#include <cuda_runtime.h>
#include <cuda_bf16.h>
#include <cuda_fp16.h>
#include <math.h>
#include <stdint.h>

// ---------------- problem constants ----------------
constexpr int NT  = 50000;
constexpr int NC  = 10000;
constexpr int H   = 4;
constexpr int HID = 256;
constexpr int E_TT = 400000;
constexpr int E_CT = 200000;
constexpr int FT = 128;
constexpr int FC = 64;
constexpr int PW = 768;        // p1|p2|pd concat width

// ---------------- device scratch ----------------
__device__ float g_ht[NT * HID];               // fp32 ht for skip connection
__device__ __half g_p16[NT * PW];              // fp16 p (logits + gather)
__device__ __half g_ps16[NC * HID];
__device__ float g_as0[NT * H], g_ad0[NT * H];
__device__ float g_as1[NT * H], g_ad1[NT * H];
__device__ float g_as2[NC * H], g_ad2[NT * H];
// CSR scratch
__device__ int g_cnt[3 * NT];
__device__ int g_cur[3 * NT];
__device__ int g_rowp[3 * (NT + 1)];
__device__ int g_col0[E_TT];
__device__ int g_col1[E_TT];
__device__ int g_col2[E_CT];
// fp16 activations
__device__ __half g_xt16[NT * FT];
__device__ __half g_xc16[NC * FC];
__device__ __half g_ht16[NT * HID];
__device__ __half g_hc16[NC * HID];
__device__ __half g_xb16[NT * HID];
// fp16 hi/lo transposed weights [N, K]
__device__ __half g_wt_hi[HID * FT],  g_wt_lo[HID * FT];
__device__ __half g_wc_hi[HID * FC],  g_wc_lo[HID * FC];
__device__ __half g_w3_hi[PW * HID],  g_w3_lo[PW * HID];   // s2d|d2s|ct_dst
__device__ __half g_ws_hi[HID * HID], g_ws_lo[HID * HID];
__device__ __half g_wo_hi[HID * HID], g_wo_lo[HID * HID];

// ---------------- fused conversion kernels ----------------
__global__ void cvt_all_kernel(const float* __restrict__ xt, const float* __restrict__ xc,
                               __half* __restrict__ xt16, __half* __restrict__ xc16) {
    const int i4 = blockIdx.x * blockDim.x + threadIdx.x;
    constexpr int N1 = NT * FT / 4;
    constexpr int N2 = NC * FC / 4;
    if (i4 >= N1 + N2) return;
    const float* src;
    __half* dst;
    int i;
    if (i4 < N1) { src = xt; dst = xt16; i = i4 * 4; }
    else { src = xc; dst = xc16; i = (i4 - N1) * 4; }
    const float4 v = *reinterpret_cast<const float4*>(src + i);
    *reinterpret_cast<__half2*>(dst + i)     = __float22half2_rn(make_float2(v.x, v.y));
    *reinterpret_cast<__half2*>(dst + i + 2) = __float22half2_rn(make_float2(v.z, v.w));
}

__global__ void splitW_all_kernel(
        const float* __restrict__ Wt, const float* __restrict__ Wc,
        const float* __restrict__ Ws2d, const float* __restrict__ Wd2s,
        const float* __restrict__ Wctd, const float* __restrict__ Wcts,
        const float* __restrict__ Wout,
        __half* __restrict__ wt_hi, __half* __restrict__ wt_lo,
        __half* __restrict__ wc_hi, __half* __restrict__ wc_lo,
        __half* __restrict__ w3_hi, __half* __restrict__ w3_lo,
        __half* __restrict__ ws_hi, __half* __restrict__ ws_lo,
        __half* __restrict__ wo_hi, __half* __restrict__ wo_lo) {
    const int idx = blockIdx.x * blockDim.x + threadIdx.x;
    constexpr int S1 = FT * HID;
    constexpr int S2 = S1 + FC * HID;
    constexpr int S3 = S2 + HID * HID;
    constexpr int S4 = S3 + HID * HID;
    constexpr int S5 = S4 + HID * HID;
    constexpr int S6 = S5 + HID * HID;
    constexpr int S7 = S6 + HID * HID;
    if (idx >= S7) return;
    const float* W; __half *hi, *lo; int K, local, nOff = 0;
    if (idx < S1)      { W = Wt;   hi = wt_hi; lo = wt_lo; K = FT;  local = idx; }
    else if (idx < S2) { W = Wc;   hi = wc_hi; lo = wc_lo; K = FC;  local = idx - S1; }
    else if (idx < S3) { W = Ws2d; hi = w3_hi; lo = w3_lo; K = HID; local = idx - S2; }
    else if (idx < S4) { W = Wd2s; hi = w3_hi; lo = w3_lo; K = HID; local = idx - S3; nOff = 256; }
    else if (idx < S5) { W = Wctd; hi = w3_hi; lo = w3_lo; K = HID; local = idx - S4; nOff = 512; }
    else if (idx < S6) { W = Wcts; hi = ws_hi; lo = ws_lo; K = HID; local = idx - S5; }
    else               { W = Wout; hi = wo_hi; lo = wo_lo; K = HID; local = idx - S6; }
    const int k = local >> 8;
    const int n = local & 255;
    const float v = W[local];
    const __half h = __float2half_rn(v);
    const __half l = __float2half_rn(v - __half2float(h));
    hi[(size_t)(nOff + n) * K + k] = h;
    lo[(size_t)(nOff + n) * K + k] = l;
}

// ---------------- CSR build ----------------
__global__ void count_kernel(const int* __restrict__ tt_src, const int* __restrict__ tt_dst,
                             const int* __restrict__ ct_dst, int* __restrict__ cnt) {
    const int e = blockIdx.x * blockDim.x + threadIdx.x;
    if (e < E_TT) {
        atomicAdd(&cnt[tt_dst[e]], 1);
        atomicAdd(&cnt[NT + tt_src[e]], 1);
    }
    if (e < E_CT) atomicAdd(&cnt[2 * NT + ct_dst[e]], 1);
}

__global__ void __launch_bounds__(1024) scan3_kernel(
        const int* __restrict__ cnt, int* __restrict__ rowp, int* __restrict__ cur) {
    const int a = blockIdx.x;
    const int* c = cnt + a * NT;
    int* rp = rowp + a * (NT + 1);
    int* cu = cur + a * NT;
    __shared__ int warp_tot[32];
    __shared__ int s_carry;
    const int tid = threadIdx.x;
    const int lane = tid & 31, wid = tid >> 5;
    if (tid == 0) s_carry = 0;
    __syncthreads();
    for (int base = 0; base < NT; base += 1024) {
        const int i = base + tid;
        const int v = (i < NT) ? c[i] : 0;
        int x = v;
#pragma unroll
        for (int o = 1; o < 32; o <<= 1) {
            const int y = __shfl_up_sync(~0u, x, o);
            if (lane >= o) x += y;
        }
        if (lane == 31) warp_tot[wid] = x;
        __syncthreads();
        if (wid == 0) {
            int t = warp_tot[lane];
#pragma unroll
            for (int o = 1; o < 32; o <<= 1) {
                const int y = __shfl_up_sync(~0u, t, o);
                if (lane >= o) t += y;
            }
            warp_tot[lane] = t;
        }
        __syncthreads();
        const int carry = s_carry;
        const int woff = (wid > 0) ? warp_tot[wid - 1] : 0;
        const int excl = carry + woff + (x - v);
        if (i < NT) { rp[i] = excl; cu[i] = excl; }
        __syncthreads();
        if (tid == 0) s_carry = carry + warp_tot[31];
        __syncthreads();
    }
    if (tid == 0) rp[NT] = s_carry;
}

__global__ void scatter_kernel(const int* __restrict__ tt_src, const int* __restrict__ tt_dst,
                               const int* __restrict__ ct_src, const int* __restrict__ ct_dst,
                               int* __restrict__ cur,
                               int* __restrict__ col0, int* __restrict__ col1,
                               int* __restrict__ col2) {
    const int e = blockIdx.x * blockDim.x + threadIdx.x;
    if (e < E_TT) {
        const int s = tt_src[e], d = tt_dst[e];
        col0[atomicAdd(&cur[d], 1)] = s;
        col1[atomicAdd(&cur[NT + s], 1)] = d;
    }
    if (e < E_CT) {
        col2[atomicAdd(&cur[2 * NT + ct_dst[e]], 1)] = ct_src[e];
    }
}

// ================= fp16 asymmetric-split tensor-core GEMM (ldmatrix) ========
constexpr int SA = 40;
constexpr int TILE_ARR = 128 * SA;
constexpr int OFF_A   = 0;
constexpr int OFF_BHI = TILE_ARR;
constexpr int OFF_BLO = 2 * TILE_ARR;
constexpr int BUF_STRIDE = 3 * TILE_ARR;
constexpr int GEMM_SMEM = 2 * BUF_STRIDE * 2; // bytes = 61440

__device__ __forceinline__ void cpa16(__half* smem, const __half* gmem) {
    uint32_t sa = (uint32_t)__cvta_generic_to_shared(smem);
    asm volatile("cp.async.ca.shared.global [%0], [%1], 16;" :: "r"(sa), "l"(gmem));
}

__device__ __forceinline__ void mma16816h(float* c, const uint32_t* a, const uint32_t* b) {
    asm volatile(
        "mma.sync.aligned.m16n8k16.row.col.f32.f16.f16.f32 "
        "{%0,%1,%2,%3}, {%4,%5,%6,%7}, {%8,%9}, {%0,%1,%2,%3};"
        : "+f"(c[0]), "+f"(c[1]), "+f"(c[2]), "+f"(c[3])
        : "r"(a[0]), "r"(a[1]), "r"(a[2]), "r"(a[3]), "r"(b[0]), "r"(b[1]));
}

__device__ __forceinline__ void ldsm4(uint32_t& r0, uint32_t& r1, uint32_t& r2,
                                      uint32_t& r3, uint32_t addr) {
    asm volatile("ldmatrix.sync.aligned.m8n8.x4.shared.b16 {%0,%1,%2,%3}, [%4];"
                 : "=r"(r0), "=r"(r1), "=r"(r2), "=r"(r3) : "r"(addr));
}

// TWOTERM: B = Bhi + Blo (2 MMA terms); else Bhi only (1 term).
template <bool BIAS, bool RELU, bool WF32, bool WF16, bool TWOTERM>
__global__ void __launch_bounds__(512, 2) mma_gemm3(
        const __half* __restrict__ A,
        const __half* __restrict__ Bhi, const __half* __restrict__ Blo,
        const float* __restrict__ bias,
        float* __restrict__ Cf32, __half* __restrict__ C16,
        int M, int N, int K) {
    extern __shared__ __align__(16) char dynsmem[];
    __half* sm = reinterpret_cast<__half*>(dynsmem);
    const uint32_t sb = (uint32_t)__cvta_generic_to_shared(sm);

    const int tid = threadIdx.x;
    const int bm = blockIdx.y * 128;
    const int bn = blockIdx.x * 128;
    const int wid = tid >> 5;
    const int lane = tid & 31;
    const int wm = wid >> 2;
    const int wn = wid & 3;
    const int g = lane >> 2;
    const int t = lane & 3;

    const int frow = tid >> 2;
    const int fkc  = (tid & 3) * 8;
    int garow = bm + frow; if (garow >= M) garow = M - 1;
    const int gbrow = bn + frow;

    const int aRow = wm * 32 + (lane & 7) + ((lane >> 3) & 1) * 8;
    const int aK   = ((lane >> 4) & 1) * 8;
    const int bRow = wn * 32 + (lane & 7) + ((lane >> 4) & 1) * 8;
    const int bK   = ((lane >> 3) & 1) * 8;
    const uint32_t aOff  = (uint32_t)(OFF_A   + aRow * SA + aK) * 2;
    const uint32_t bhOff = (uint32_t)(OFF_BHI + bRow * SA + bK) * 2;
    const uint32_t blOff = (uint32_t)(OFF_BLO + bRow * SA + bK) * 2;

    float acc[2][4][4];
#pragma unroll
    for (int mi = 0; mi < 2; mi++)
#pragma unroll
        for (int ni = 0; ni < 4; ni++)
#pragma unroll
            for (int r = 0; r < 4; r++) acc[mi][ni][r] = 0.f;

    const int KT = K >> 5;
    {
        const size_t ao = (size_t)garow * K + fkc;
        const size_t bo = (size_t)gbrow * K + fkc;
        __half* b0 = sm;
        cpa16(b0 + OFF_A   + frow * SA + fkc, A + ao);
        cpa16(b0 + OFF_BHI + frow * SA + fkc, Bhi + bo);
        if (TWOTERM) cpa16(b0 + OFF_BLO + frow * SA + fkc, Blo + bo);
        asm volatile("cp.async.commit_group;");
    }

    for (int kt = 0; kt < KT; kt++) {
        asm volatile("cp.async.wait_group 0;");
        __syncthreads();
        if (kt + 1 < KT) {
            const int k0 = (kt + 1) << 5;
            const size_t ao = (size_t)garow * K + k0 + fkc;
            const size_t bo = (size_t)gbrow * K + k0 + fkc;
            __half* nb = sm + ((kt + 1) & 1) * BUF_STRIDE;
            cpa16(nb + OFF_A   + frow * SA + fkc, A + ao);
            cpa16(nb + OFF_BHI + frow * SA + fkc, Bhi + bo);
            if (TWOTERM) cpa16(nb + OFF_BLO + frow * SA + fkc, Blo + bo);
            asm volatile("cp.async.commit_group;");
        }
        const uint32_t bufb = sb + ((kt & 1) * BUF_STRIDE) * 2;

#pragma unroll
        for (int ks = 0; ks < 2; ks++) {
            const uint32_t kByte = (uint32_t)(ks * 16) * 2;
            uint32_t bh[4][2], bl[4][2];
            const uint32_t bhAddr = bufb + bhOff + kByte;
            ldsm4(bh[0][0], bh[0][1], bh[1][0], bh[1][1], bhAddr);
            ldsm4(bh[2][0], bh[2][1], bh[3][0], bh[3][1], bhAddr + 16 * SA * 2);
            if (TWOTERM) {
                const uint32_t blAddr = bufb + blOff + kByte;
                ldsm4(bl[0][0], bl[0][1], bl[1][0], bl[1][1], blAddr);
                ldsm4(bl[2][0], bl[2][1], bl[3][0], bl[3][1], blAddr + 16 * SA * 2);
            }
            const uint32_t aAddr0 = bufb + aOff + kByte;
#pragma unroll
            for (int mi = 0; mi < 2; mi++) {
                uint32_t a[4];
                ldsm4(a[0], a[1], a[2], a[3], aAddr0 + (uint32_t)(mi * 16 * SA) * 2);
#pragma unroll
                for (int ni = 0; ni < 4; ni++) {
                    mma16816h(acc[mi][ni], a, bh[ni]);
                    if (TWOTERM) mma16816h(acc[mi][ni], a, bl[ni]);
                }
            }
        }
    }

#pragma unroll
    for (int mi = 0; mi < 2; mi++) {
        const int row0 = bm + wm * 32 + mi * 16 + g;
#pragma unroll
        for (int ni = 0; ni < 4; ni++) {
            const int col = bn + wn * 32 + ni * 8 + 2 * t;
            float c0 = acc[mi][ni][0], c1 = acc[mi][ni][1];
            float c2 = acc[mi][ni][2], c3 = acc[mi][ni][3];
            if (BIAS) {
                const float b0 = bias[col], b1 = bias[col + 1];
                c0 += b0; c1 += b1; c2 += b0; c3 += b1;
            }
            if (RELU) {
                c0 = fmaxf(c0, 0.f); c1 = fmaxf(c1, 0.f);
                c2 = fmaxf(c2, 0.f); c3 = fmaxf(c3, 0.f);
            }
#pragma unroll
            for (int rr = 0; rr < 2; rr++) {
                const int row = row0 + rr * 8;
                if (row >= M) continue;
                const float v0 = rr ? c2 : c0;
                const float v1 = rr ? c3 : c1;
                const size_t off = (size_t)row * N + col;
                if (WF32)
                    *reinterpret_cast<float2*>(Cf32 + off) = make_float2(v0, v1);
                if (WF16)
                    *reinterpret_cast<__half2*>(C16 + off) =
                        __float22half2_rn(make_float2(v0, v1));
            }
        }
    }
}

// ---------------- alpha kernels (fp16 p reads) ----------------
__global__ void alpha_kernel(const __half* __restrict__ p, int stride,
                             const float* __restrict__ att,
                             float* __restrict__ out, int N) {
    const int gw = (blockIdx.x * blockDim.x + threadIdx.x) >> 5;
    const int lane = threadIdx.x & 31;
    if (gw >= N * H) return;
    const int n = gw >> 2;
    const int h = gw & 3;
    const __half* pr = p + (size_t)n * stride + h * 64;
    const float* at = att + h * 64;
    float s = __half2float(pr[lane]) * at[lane] +
              __half2float(pr[lane + 32]) * at[lane + 32];
#pragma unroll
    for (int o = 16; o > 0; o >>= 1) s += __shfl_xor_sync(0xffffffffu, s, o);
    if (lane == 0) out[gw] = s;
}

__global__ void alpha5_kernel(const __half* __restrict__ p,
                              const float* __restrict__ a_s0, const float* __restrict__ a_d0,
                              const float* __restrict__ a_s1, const float* __restrict__ a_d1,
                              const float* __restrict__ a_d2,
                              float* __restrict__ as0, float* __restrict__ ad0,
                              float* __restrict__ as1, float* __restrict__ ad1,
                              float* __restrict__ ad2) {
    const int gw = (blockIdx.x * blockDim.x + threadIdx.x) >> 5;
    const int lane = threadIdx.x & 31;
    if (gw >= NT * H) return;
    const int n = gw >> 2;
    const int h = gw & 3;
    const __half* r1 = p + (size_t)n * PW + h * 64;
    const __half* r2 = r1 + 256;
    const __half* r3 = r1 + 512;
    const float x1a = __half2float(r1[lane]), x1b = __half2float(r1[lane + 32]);
    const float x2a = __half2float(r2[lane]), x2b = __half2float(r2[lane + 32]);
    const float x3a = __half2float(r3[lane]), x3b = __half2float(r3[lane + 32]);
    const float* v;
    v = a_s0 + h * 64; float s0 = x1a * v[lane] + x1b * v[lane + 32];
    v = a_d0 + h * 64; float s1 = x1a * v[lane] + x1b * v[lane + 32];
    v = a_s1 + h * 64; float s2 = x2a * v[lane] + x2b * v[lane + 32];
    v = a_d1 + h * 64; float s3 = x2a * v[lane] + x2b * v[lane + 32];
    v = a_d2 + h * 64; float s4 = x3a * v[lane] + x3b * v[lane + 32];
#pragma unroll
    for (int o = 16; o > 0; o >>= 1) {
        s0 += __shfl_xor_sync(0xffffffffu, s0, o);
        s1 += __shfl_xor_sync(0xffffffffu, s1, o);
        s2 += __shfl_xor_sync(0xffffffffu, s2, o);
        s3 += __shfl_xor_sync(0xffffffffu, s3, o);
        s4 += __shfl_xor_sync(0xffffffffu, s4, o);
    }
    if (lane == 0) { as0[gw] = s0; ad0[gw] = s1; as1[gw] = s2; ad1[gw] = s3; ad2[gw] = s4; }
}

// ---------------- fused CSR gather + combine ----------------
__device__ __forceinline__ void acc8_raw(float* acc, float ex, uint4 raw) {
    const __half2* hp = reinterpret_cast<const __half2*>(&raw);
    const float2 f0 = __half22float2(hp[0]);
    const float2 f1 = __half22float2(hp[1]);
    const float2 f2 = __half22float2(hp[2]);
    const float2 f3 = __half22float2(hp[3]);
    acc[0] += ex * f0.x; acc[1] += ex * f0.y;
    acc[2] += ex * f1.x; acc[3] += ex * f1.y;
    acc[4] += ex * f2.x; acc[5] += ex * f2.y;
    acc[6] += ex * f3.x; acc[7] += ex * f3.y;
}
__device__ __forceinline__ float lrelu_exp(float a) {
    a = a > 0.f ? a : 0.2f * a;
    return __expf(a);
}

template <int STRIDE>
__device__ __forceinline__ void gat_pass(
        const int* __restrict__ col, int e0, int e1,
        const float* __restrict__ asrc, float adn, int h,
        const __half* __restrict__ xbase, int k,
        float* acc, float& den) {
    int e = e0;
    for (; e + 4 <= e1; e += 4) {
        const int s0 = __ldg(col + e);
        const int s1 = __ldg(col + e + 1);
        const int s2 = __ldg(col + e + 2);
        const int s3 = __ldg(col + e + 3);
        const float l0 = __ldg(asrc + s0 * 4 + h);
        const float l1 = __ldg(asrc + s1 * 4 + h);
        const float l2 = __ldg(asrc + s2 * 4 + h);
        const float l3 = __ldg(asrc + s3 * 4 + h);
        const uint4 r0 = *reinterpret_cast<const uint4*>(xbase + (size_t)s0 * STRIDE + k);
        const uint4 r1 = *reinterpret_cast<const uint4*>(xbase + (size_t)s1 * STRIDE + k);
        const uint4 r2 = *reinterpret_cast<const uint4*>(xbase + (size_t)s2 * STRIDE + k);
        const uint4 r3 = *reinterpret_cast<const uint4*>(xbase + (size_t)s3 * STRIDE + k);
        const float e0x = lrelu_exp(l0 + adn);
        const float e1x = lrelu_exp(l1 + adn);
        const float e2x = lrelu_exp(l2 + adn);
        const float e3x = lrelu_exp(l3 + adn);
        den += (e0x + e1x) + (e2x + e3x);
        acc8_raw(acc, e0x, r0);
        acc8_raw(acc, e1x, r1);
        acc8_raw(acc, e2x, r2);
        acc8_raw(acc, e3x, r3);
    }
    for (; e < e1; e++) {
        const int s = __ldg(col + e);
        const float ex = lrelu_exp(__ldg(asrc + s * 4 + h) + adn);
        const uint4 r = *reinterpret_cast<const uint4*>(xbase + (size_t)s * STRIDE + k);
        den += ex;
        acc8_raw(acc, ex, r);
    }
}

__global__ void __launch_bounds__(256) gat_gather(
        const int* __restrict__ rowp,
        const int* __restrict__ col0, const int* __restrict__ col1,
        const int* __restrict__ col2,
        const float* __restrict__ as0, const float* __restrict__ ad0,
        const float* __restrict__ as1, const float* __restrict__ ad1,
        const float* __restrict__ as2, const float* __restrict__ ad2,
        const __half* __restrict__ p16, const __half* __restrict__ ps16,
        const float* __restrict__ ht,
        const float* __restrict__ b1, const float* __restrict__ b2,
        const float* __restrict__ b3,
        __half* __restrict__ xb16) {
    const int n = (blockIdx.x * blockDim.x + threadIdx.x) >> 5;
    if (n >= NT) return;
    const int lane = threadIdx.x & 31;
    const int h = lane >> 3;
    const int k = lane * 8;

    const int* rp0 = rowp;
    const int* rp1 = rowp + (NT + 1);
    const int* rp2 = rowp + 2 * (NT + 1);

    float xacc[8];
    float acc[8];

    {
#pragma unroll
        for (int j = 0; j < 8; j++) acc[j] = 0.f;
        float den = 0.f;
        const float adn = ad0[n * 4 + h];
        gat_pass<PW>(col0, rp0[n], rp0[n + 1], as0, adn, h, p16, k, acc, den);
        {
            const float ex = lrelu_exp(as0[n * 4 + h] + adn);
            const uint4 r = *reinterpret_cast<const uint4*>(p16 + (size_t)n * PW + k);
            den += ex;
            acc8_raw(acc, ex, r);
        }
        const float r = 0.25f / fmaxf(den, 1e-16f);
#pragma unroll
        for (int j = 0; j < 8; j++) xacc[j] = r * acc[j];
    }

    {
#pragma unroll
        for (int j = 0; j < 8; j++) acc[j] = 0.f;
        float den = 0.f;
        const float adn = ad1[n * 4 + h];
        gat_pass<PW>(col1, rp1[n], rp1[n + 1], as1, adn, h, p16 + 256, k, acc, den);
        {
            const float ex = lrelu_exp(as1[n * 4 + h] + adn);
            const uint4 r = *reinterpret_cast<const uint4*>(p16 + (size_t)n * PW + 256 + k);
            den += ex;
            acc8_raw(acc, ex, r);
        }
        const float r = 0.25f / fmaxf(den, 1e-16f);
#pragma unroll
        for (int j = 0; j < 8; j++) xacc[j] += r * acc[j];
    }

    {
#pragma unroll
        for (int j = 0; j < 8; j++) acc[j] = 0.f;
        float den = 0.f;
        const float adn = ad2[n * 4 + h];
        gat_pass<HID>(col2, rp2[n], rp2[n + 1], as2, adn, h, ps16, k, acc, den);
        const float r = 0.5f / fmaxf(den, 1e-16f);
#pragma unroll
        for (int j = 0; j < 8; j++) xacc[j] += r * acc[j];
    }

    const float4 b1a = *reinterpret_cast<const float4*>(b1 + k);
    const float4 b1b = *reinterpret_cast<const float4*>(b1 + k + 4);
    const float4 b2a = *reinterpret_cast<const float4*>(b2 + k);
    const float4 b2b = *reinterpret_cast<const float4*>(b2 + k + 4);
    const float4 b3a = *reinterpret_cast<const float4*>(b3 + k);
    const float4 b3b = *reinterpret_cast<const float4*>(b3 + k + 4);
    const float4 h0 = *reinterpret_cast<const float4*>(ht + (size_t)n * HID + k);
    const float4 h1 = *reinterpret_cast<const float4*>(ht + (size_t)n * HID + k + 4);
    float xv[8];
    xv[0] = xacc[0] + 0.25f * (b1a.x + b2a.x) + 0.5f * b3a.x + h0.x;
    xv[1] = xacc[1] + 0.25f * (b1a.y + b2a.y) + 0.5f * b3a.y + h0.y;
    xv[2] = xacc[2] + 0.25f * (b1a.z + b2a.z) + 0.5f * b3a.z + h0.z;
    xv[3] = xacc[3] + 0.25f * (b1a.w + b2a.w) + 0.5f * b3a.w + h0.w;
    xv[4] = xacc[4] + 0.25f * (b1b.x + b2b.x) + 0.5f * b3b.x + h1.x;
    xv[5] = xacc[5] + 0.25f * (b1b.y + b2b.y) + 0.5f * b3b.y + h1.y;
    xv[6] = xacc[6] + 0.25f * (b1b.z + b2b.z) + 0.5f * b3b.z + h1.z;
    xv[7] = xacc[7] + 0.25f * (b1b.w + b2b.w) + 0.5f * b3b.w + h1.w;
    uint4 u;
    __half2* up = reinterpret_cast<__half2*>(&u);
#pragma unroll
    for (int j = 0; j < 4; j++) {
        const float a = fmaxf(xv[2 * j], 0.f);
        const float b = fmaxf(xv[2 * j + 1], 0.f);
        up[j] = __float22half2_rn(make_float2(a, b));
    }
    *reinterpret_cast<uint4*>(xb16 + (size_t)n * HID + k) = u;
}

// ---------------- launch ----------------
extern "C" void kernel_launch(void* const* d_in, const int* in_sizes, int n_in,
                              void* d_out, int out_size) {
    const float* x_target = (const float*)d_in[0];
    const float* x_context = (const float*)d_in[1];
    const int*   ei_tt     = (const int*)d_in[2];
    const int*   ei_ct_src = (const int*)d_in[3];
    const int*   ei_ct_dst = (const int*)d_in[4];
    const float* Wt = (const float*)d_in[5];
    const float* bt = (const float*)d_in[6];
    const float* Wc = (const float*)d_in[7];
    const float* bc = (const float*)d_in[8];
    const float* W_s2d  = (const float*)d_in[9];
    const float* as_s2d = (const float*)d_in[10];
    const float* ad_s2d = (const float*)d_in[11];
    const float* b_s2d  = (const float*)d_in[12];
    const float* W_d2s  = (const float*)d_in[13];
    const float* as_d2s = (const float*)d_in[14];
    const float* ad_d2s = (const float*)d_in[15];
    const float* b_d2s  = (const float*)d_in[16];
    const float* W_ct_src = (const float*)d_in[17];
    const float* W_ct_dst = (const float*)d_in[18];
    const float* as_ct  = (const float*)d_in[19];
    const float* ad_ct  = (const float*)d_in[20];
    const float* b_ct   = (const float*)d_in[21];
    const float* W_out  = (const float*)d_in[22];
    const float* b_out  = (const float*)d_in[23];

    float *ht, *as0, *ad0, *as1, *ad1, *as2, *ad2;
    cudaGetSymbolAddress((void**)&ht,  g_ht);
    cudaGetSymbolAddress((void**)&as0, g_as0);
    cudaGetSymbolAddress((void**)&ad0, g_ad0);
    cudaGetSymbolAddress((void**)&as1, g_as1);
    cudaGetSymbolAddress((void**)&ad1, g_ad1);
    cudaGetSymbolAddress((void**)&as2, g_as2);
    cudaGetSymbolAddress((void**)&ad2, g_ad2);

    __half *p16, *ps16, *xt16, *xc16, *ht16, *hc16, *xb16;
    cudaGetSymbolAddress((void**)&p16,  g_p16);
    cudaGetSymbolAddress((void**)&ps16, g_ps16);
    cudaGetSymbolAddress((void**)&xt16, g_xt16);
    cudaGetSymbolAddress((void**)&xc16, g_xc16);
    cudaGetSymbolAddress((void**)&ht16, g_ht16);
    cudaGetSymbolAddress((void**)&hc16, g_hc16);
    cudaGetSymbolAddress((void**)&xb16, g_xb16);

    int *cnt, *cur, *rowp, *col0, *col1, *col2;
    cudaGetSymbolAddress((void**)&cnt,  g_cnt);
    cudaGetSymbolAddress((void**)&cur,  g_cur);
    cudaGetSymbolAddress((void**)&rowp, g_rowp);
    cudaGetSymbolAddress((void**)&col0, g_col0);
    cudaGetSymbolAddress((void**)&col1, g_col1);
    cudaGetSymbolAddress((void**)&col2, g_col2);

    __half *wt_hi, *wt_lo, *wc_hi, *wc_lo, *w3_hi, *w3_lo, *ws_hi, *ws_lo, *wo_hi, *wo_lo;
    cudaGetSymbolAddress((void**)&wt_hi, g_wt_hi); cudaGetSymbolAddress((void**)&wt_lo, g_wt_lo);
    cudaGetSymbolAddress((void**)&wc_hi, g_wc_hi); cudaGetSymbolAddress((void**)&wc_lo, g_wc_lo);
    cudaGetSymbolAddress((void**)&w3_hi, g_w3_hi); cudaGetSymbolAddress((void**)&w3_lo, g_w3_lo);
    cudaGetSymbolAddress((void**)&ws_hi, g_ws_hi); cudaGetSymbolAddress((void**)&ws_lo, g_ws_lo);
    cudaGetSymbolAddress((void**)&wo_hi, g_wo_hi); cudaGetSymbolAddress((void**)&wo_lo, g_wo_lo);

    // one-time setup (first call is the uncaptured correctness run)
    static cudaStream_t s1 = nullptr, s2 = nullptr;
    static cudaEvent_t eFork = nullptr, eConv = nullptr, eS1 = nullptr, eS2 = nullptr;
    static bool init_done = false;
    if (!init_done) {
        cudaFuncSetAttribute(mma_gemm3<true, true, true, true, true>,
                             cudaFuncAttributeMaxDynamicSharedMemorySize, GEMM_SMEM);
        cudaFuncSetAttribute(mma_gemm3<true, true, false, true, true>,
                             cudaFuncAttributeMaxDynamicSharedMemorySize, GEMM_SMEM);
        cudaFuncSetAttribute(mma_gemm3<false, false, false, true, false>,
                             cudaFuncAttributeMaxDynamicSharedMemorySize, GEMM_SMEM);
        cudaFuncSetAttribute(mma_gemm3<true, false, true, false, true>,
                             cudaFuncAttributeMaxDynamicSharedMemorySize, GEMM_SMEM);
        cudaStreamCreateWithFlags(&s1, cudaStreamNonBlocking);
        cudaStreamCreateWithFlags(&s2, cudaStreamNonBlocking);
        cudaEventCreateWithFlags(&eFork, cudaEventDisableTiming);
        cudaEventCreateWithFlags(&eConv, cudaEventDisableTiming);
        cudaEventCreateWithFlags(&eS1, cudaEventDisableTiming);
        cudaEventCreateWithFlags(&eS2, cudaEventDisableTiming);
        init_done = true;
    }

    const int* tt_src = ei_tt;
    const int* tt_dst = ei_tt + E_TT;

    const dim3 blk(512);
    const dim3 g_ht_g(HID / 128, (NT + 127) / 128);
    const dim3 g_hc_g(HID / 128, (NC + 127) / 128);
    const dim3 g_p_g(PW / 128, (NT + 127) / 128);

    // ---- fork point ----
    cudaEventRecord(eFork, 0);
    cudaStreamWaitEvent(s1, eFork, 0);
    cudaStreamWaitEvent(s2, eFork, 0);

    // ---- stream s2: CSR build (independent of everything else) ----
    cudaMemsetAsync(cnt, 0, sizeof(int) * 3 * NT, s2);
    count_kernel<<<(E_TT + 255) / 256, 256, 0, s2>>>(tt_src, tt_dst, ei_ct_dst, cnt);
    scan3_kernel<<<3, 1024, 0, s2>>>(cnt, rowp, cur);
    scatter_kernel<<<(E_TT + 255) / 256, 256, 0, s2>>>(tt_src, tt_dst, ei_ct_src,
                                                       ei_ct_dst, cur, col0, col1, col2);
    cudaEventRecord(eS2, s2);

    // ---- stream 0: conversions ----
    {
        const int ncvt = (NT * FT + NC * FC) / 4;
        cvt_all_kernel<<<(ncvt + 255) / 256, 256>>>(x_target, x_context, xt16, xc16);
    }
    splitW_all_kernel<<<(376832 + 255) / 256, 256>>>(
        Wt, Wc, W_s2d, W_d2s, W_ct_dst, W_ct_src, W_out,
        wt_hi, wt_lo, wc_hi, wc_lo, w3_hi, w3_lo, ws_hi, ws_lo, wo_hi, wo_lo);
    cudaEventRecord(eConv, 0);

    // ---- stream s1: small context chain (hc -> ps -> alpha(ps)) ----
    cudaStreamWaitEvent(s1, eConv, 0);
    mma_gemm3<true, true, false, true, true><<<g_hc_g, blk, GEMM_SMEM, s1>>>(
        xc16, wc_hi, wc_lo, bc, nullptr, hc16, NC, HID, FC);
    mma_gemm3<false, false, false, true, false><<<g_hc_g, blk, GEMM_SMEM, s1>>>(
        hc16, ws_hi, nullptr, nullptr, nullptr, ps16, NC, HID, HID);
    alpha_kernel<<<(NC * H * 32 + 255) / 256, 256, 0, s1>>>(ps16, HID, as_ct, as2, NC);
    cudaEventRecord(eS1, s1);

    // ---- stream 0: big target chain (p-GEMM single-term) ----
    mma_gemm3<true, true, true, true, true><<<g_ht_g, blk, GEMM_SMEM>>>(
        xt16, wt_hi, wt_lo, bt, ht, ht16, NT, HID, FT);
    mma_gemm3<false, false, false, true, false><<<g_p_g, blk, GEMM_SMEM>>>(
        ht16, w3_hi, nullptr, nullptr, nullptr, p16, NT, PW, HID);
    alpha5_kernel<<<(NT * H * 32 + 255) / 256, 256>>>(
        p16, as_s2d, ad_s2d, as_d2s, ad_d2s, ad_ct, as0, ad0, as1, ad1, ad2);

    // ---- join ----
    cudaStreamWaitEvent(0, eS1, 0);
    cudaStreamWaitEvent(0, eS2, 0);

    // ---- fused gather + combine ----
    gat_gather<<<(NT * 32 + 255) / 256, 256>>>(
        rowp, col0, col1, col2, as0, ad0, as1, ad1, as2, ad2,
        p16, ps16, ht, b_s2d, b_d2s, b_ct, xb16);

    // ---- final linear ----
    mma_gemm3<true, false, true, false, true><<<g_ht_g, blk, GEMM_SMEM>>>(
        xb16, wo_hi, wo_lo, b_out, (float*)d_out, nullptr, NT, HID, HID);
}

// round 15
// speedup vs baseline: 1.2153x; 1.0720x over previous
#include <cuda_runtime.h>
#include <cuda_bf16.h>
#include <cuda_fp16.h>
#include <math.h>
#include <stdint.h>

// ---------------- problem constants ----------------
constexpr int NT  = 50000;
constexpr int NC  = 10000;
constexpr int H   = 4;
constexpr int HID = 256;
constexpr int E_TT = 400000;
constexpr int E_CT = 200000;
constexpr int FT = 128;
constexpr int FC = 64;
constexpr int PW = 768;        // p1|p2|pd concat width

// ---------------- device scratch ----------------
__device__ float g_ht[NT * HID];               // fp32 ht for skip connection
__device__ __half g_p16[NT * PW];              // fp16 p (logits + gather)
__device__ __half g_ps16[NC * HID];
__device__ float g_as0[NT * H], g_ad0[NT * H];
__device__ float g_as1[NT * H], g_ad1[NT * H];
__device__ float g_as2[NC * H], g_ad2[NT * H];
// CSR scratch
__device__ int g_cnt[3 * NT];
__device__ int g_cur[3 * NT];
__device__ int g_rowp[3 * (NT + 1)];
__device__ int g_col0[E_TT];
__device__ int g_col1[E_TT];
__device__ int g_col2[E_CT];
// fp16 activations
__device__ __half g_xt16[NT * FT];
__device__ __half g_xc16[NC * FC];
__device__ __half g_ht16[NT * HID];
__device__ __half g_hc16[NC * HID];
__device__ __half g_xb16[NT * HID];
// fp16 hi/lo transposed weights [N, K]
__device__ __half g_wt_hi[HID * FT],  g_wt_lo[HID * FT];
__device__ __half g_wc_hi[HID * FC],  g_wc_lo[HID * FC];
__device__ __half g_w3_hi[PW * HID],  g_w3_lo[PW * HID];   // s2d|d2s|ct_dst
__device__ __half g_ws_hi[HID * HID], g_ws_lo[HID * HID];
__device__ __half g_wo_hi[HID * HID], g_wo_lo[HID * HID];

// ---------------- fused conversion kernels ----------------
__global__ void cvt_all_kernel(const float* __restrict__ xt, const float* __restrict__ xc,
                               __half* __restrict__ xt16, __half* __restrict__ xc16) {
    const int i4 = blockIdx.x * blockDim.x + threadIdx.x;
    constexpr int N1 = NT * FT / 4;
    constexpr int N2 = NC * FC / 4;
    if (i4 >= N1 + N2) return;
    const float* src;
    __half* dst;
    int i;
    if (i4 < N1) { src = xt; dst = xt16; i = i4 * 4; }
    else { src = xc; dst = xc16; i = (i4 - N1) * 4; }
    const float4 v = *reinterpret_cast<const float4*>(src + i);
    *reinterpret_cast<__half2*>(dst + i)     = __float22half2_rn(make_float2(v.x, v.y));
    *reinterpret_cast<__half2*>(dst + i + 2) = __float22half2_rn(make_float2(v.z, v.w));
}

__global__ void splitW_all_kernel(
        const float* __restrict__ Wt, const float* __restrict__ Wc,
        const float* __restrict__ Ws2d, const float* __restrict__ Wd2s,
        const float* __restrict__ Wctd, const float* __restrict__ Wcts,
        const float* __restrict__ Wout,
        __half* __restrict__ wt_hi, __half* __restrict__ wt_lo,
        __half* __restrict__ wc_hi, __half* __restrict__ wc_lo,
        __half* __restrict__ w3_hi, __half* __restrict__ w3_lo,
        __half* __restrict__ ws_hi, __half* __restrict__ ws_lo,
        __half* __restrict__ wo_hi, __half* __restrict__ wo_lo) {
    const int idx = blockIdx.x * blockDim.x + threadIdx.x;
    constexpr int S1 = FT * HID;
    constexpr int S2 = S1 + FC * HID;
    constexpr int S3 = S2 + HID * HID;
    constexpr int S4 = S3 + HID * HID;
    constexpr int S5 = S4 + HID * HID;
    constexpr int S6 = S5 + HID * HID;
    constexpr int S7 = S6 + HID * HID;
    if (idx >= S7) return;
    const float* W; __half *hi, *lo; int K, local, nOff = 0;
    if (idx < S1)      { W = Wt;   hi = wt_hi; lo = wt_lo; K = FT;  local = idx; }
    else if (idx < S2) { W = Wc;   hi = wc_hi; lo = wc_lo; K = FC;  local = idx - S1; }
    else if (idx < S3) { W = Ws2d; hi = w3_hi; lo = w3_lo; K = HID; local = idx - S2; }
    else if (idx < S4) { W = Wd2s; hi = w3_hi; lo = w3_lo; K = HID; local = idx - S3; nOff = 256; }
    else if (idx < S5) { W = Wctd; hi = w3_hi; lo = w3_lo; K = HID; local = idx - S4; nOff = 512; }
    else if (idx < S6) { W = Wcts; hi = ws_hi; lo = ws_lo; K = HID; local = idx - S5; }
    else               { W = Wout; hi = wo_hi; lo = wo_lo; K = HID; local = idx - S6; }
    const int k = local >> 8;
    const int n = local & 255;
    const float v = W[local];
    const __half h = __float2half_rn(v);
    const __half l = __float2half_rn(v - __half2float(h));
    hi[(size_t)(nOff + n) * K + k] = h;
    lo[(size_t)(nOff + n) * K + k] = l;
}

// ---------------- CSR build ----------------
__global__ void count_kernel(const int* __restrict__ tt_src, const int* __restrict__ tt_dst,
                             const int* __restrict__ ct_dst, int* __restrict__ cnt) {
    const int e = blockIdx.x * blockDim.x + threadIdx.x;
    if (e < E_TT) {
        atomicAdd(&cnt[tt_dst[e]], 1);
        atomicAdd(&cnt[NT + tt_src[e]], 1);
    }
    if (e < E_CT) atomicAdd(&cnt[2 * NT + ct_dst[e]], 1);
}

__global__ void __launch_bounds__(1024) scan3_kernel(
        const int* __restrict__ cnt, int* __restrict__ rowp, int* __restrict__ cur) {
    const int a = blockIdx.x;
    const int* c = cnt + a * NT;
    int* rp = rowp + a * (NT + 1);
    int* cu = cur + a * NT;
    __shared__ int warp_tot[32];
    __shared__ int s_carry;
    const int tid = threadIdx.x;
    const int lane = tid & 31, wid = tid >> 5;
    if (tid == 0) s_carry = 0;
    __syncthreads();
    for (int base = 0; base < NT; base += 1024) {
        const int i = base + tid;
        const int v = (i < NT) ? c[i] : 0;
        int x = v;
#pragma unroll
        for (int o = 1; o < 32; o <<= 1) {
            const int y = __shfl_up_sync(~0u, x, o);
            if (lane >= o) x += y;
        }
        if (lane == 31) warp_tot[wid] = x;
        __syncthreads();
        if (wid == 0) {
            int t = warp_tot[lane];
#pragma unroll
            for (int o = 1; o < 32; o <<= 1) {
                const int y = __shfl_up_sync(~0u, t, o);
                if (lane >= o) t += y;
            }
            warp_tot[lane] = t;
        }
        __syncthreads();
        const int carry = s_carry;
        const int woff = (wid > 0) ? warp_tot[wid - 1] : 0;
        const int excl = carry + woff + (x - v);
        if (i < NT) { rp[i] = excl; cu[i] = excl; }
        __syncthreads();
        if (tid == 0) s_carry = carry + warp_tot[31];
        __syncthreads();
    }
    if (tid == 0) rp[NT] = s_carry;
}

__global__ void scatter_kernel(const int* __restrict__ tt_src, const int* __restrict__ tt_dst,
                               const int* __restrict__ ct_src, const int* __restrict__ ct_dst,
                               int* __restrict__ cur,
                               int* __restrict__ col0, int* __restrict__ col1,
                               int* __restrict__ col2) {
    const int e = blockIdx.x * blockDim.x + threadIdx.x;
    if (e < E_TT) {
        const int s = tt_src[e], d = tt_dst[e];
        col0[atomicAdd(&cur[d], 1)] = s;
        col1[atomicAdd(&cur[NT + s], 1)] = d;
    }
    if (e < E_CT) {
        col2[atomicAdd(&cur[2 * NT + ct_dst[e]], 1)] = ct_src[e];
    }
}

// ================= fp16 asymmetric-split tensor-core GEMM (ldmatrix) ========
constexpr int SA = 40;
constexpr int TILE_ARR = 128 * SA;
constexpr int OFF_A   = 0;
constexpr int OFF_BHI = TILE_ARR;
constexpr int OFF_BLO = 2 * TILE_ARR;
constexpr int BUF_STRIDE = 3 * TILE_ARR;
constexpr int GEMM_SMEM = 2 * BUF_STRIDE * 2; // bytes = 61440

__device__ __forceinline__ void cpa16(__half* smem, const __half* gmem) {
    uint32_t sa = (uint32_t)__cvta_generic_to_shared(smem);
    asm volatile("cp.async.ca.shared.global [%0], [%1], 16;" :: "r"(sa), "l"(gmem));
}

__device__ __forceinline__ void mma16816h(float* c, const uint32_t* a, const uint32_t* b) {
    asm volatile(
        "mma.sync.aligned.m16n8k16.row.col.f32.f16.f16.f32 "
        "{%0,%1,%2,%3}, {%4,%5,%6,%7}, {%8,%9}, {%0,%1,%2,%3};"
        : "+f"(c[0]), "+f"(c[1]), "+f"(c[2]), "+f"(c[3])
        : "r"(a[0]), "r"(a[1]), "r"(a[2]), "r"(a[3]), "r"(b[0]), "r"(b[1]));
}

__device__ __forceinline__ void ldsm4(uint32_t& r0, uint32_t& r1, uint32_t& r2,
                                      uint32_t& r3, uint32_t addr) {
    asm volatile("ldmatrix.sync.aligned.m8n8.x4.shared.b16 {%0,%1,%2,%3}, [%4];"
                 : "=r"(r0), "=r"(r1), "=r"(r2), "=r"(r3) : "r"(addr));
}

// TWOTERM: B = Bhi + Blo (2 MMA terms); else Bhi only (1 term).
template <bool BIAS, bool RELU, bool WF32, bool WF16, bool TWOTERM>
__global__ void __launch_bounds__(512, 2) mma_gemm3(
        const __half* __restrict__ A,
        const __half* __restrict__ Bhi, const __half* __restrict__ Blo,
        const float* __restrict__ bias,
        float* __restrict__ Cf32, __half* __restrict__ C16,
        int M, int N, int K) {
    extern __shared__ __align__(16) char dynsmem[];
    __half* sm = reinterpret_cast<__half*>(dynsmem);
    const uint32_t sb = (uint32_t)__cvta_generic_to_shared(sm);

    const int tid = threadIdx.x;
    const int bm = blockIdx.y * 128;
    const int bn = blockIdx.x * 128;
    const int wid = tid >> 5;
    const int lane = tid & 31;
    const int wm = wid >> 2;
    const int wn = wid & 3;
    const int g = lane >> 2;
    const int t = lane & 3;

    const int frow = tid >> 2;
    const int fkc  = (tid & 3) * 8;
    int garow = bm + frow; if (garow >= M) garow = M - 1;
    const int gbrow = bn + frow;

    const int aRow = wm * 32 + (lane & 7) + ((lane >> 3) & 1) * 8;
    const int aK   = ((lane >> 4) & 1) * 8;
    const int bRow = wn * 32 + (lane & 7) + ((lane >> 4) & 1) * 8;
    const int bK   = ((lane >> 3) & 1) * 8;
    const uint32_t aOff  = (uint32_t)(OFF_A   + aRow * SA + aK) * 2;
    const uint32_t bhOff = (uint32_t)(OFF_BHI + bRow * SA + bK) * 2;
    const uint32_t blOff = (uint32_t)(OFF_BLO + bRow * SA + bK) * 2;

    float acc[2][4][4];
#pragma unroll
    for (int mi = 0; mi < 2; mi++)
#pragma unroll
        for (int ni = 0; ni < 4; ni++)
#pragma unroll
            for (int r = 0; r < 4; r++) acc[mi][ni][r] = 0.f;

    const int KT = K >> 5;
    {
        const size_t ao = (size_t)garow * K + fkc;
        const size_t bo = (size_t)gbrow * K + fkc;
        __half* b0 = sm;
        cpa16(b0 + OFF_A   + frow * SA + fkc, A + ao);
        cpa16(b0 + OFF_BHI + frow * SA + fkc, Bhi + bo);
        if (TWOTERM) cpa16(b0 + OFF_BLO + frow * SA + fkc, Blo + bo);
        asm volatile("cp.async.commit_group;");
    }

    for (int kt = 0; kt < KT; kt++) {
        asm volatile("cp.async.wait_group 0;");
        __syncthreads();
        if (kt + 1 < KT) {
            const int k0 = (kt + 1) << 5;
            const size_t ao = (size_t)garow * K + k0 + fkc;
            const size_t bo = (size_t)gbrow * K + k0 + fkc;
            __half* nb = sm + ((kt + 1) & 1) * BUF_STRIDE;
            cpa16(nb + OFF_A   + frow * SA + fkc, A + ao);
            cpa16(nb + OFF_BHI + frow * SA + fkc, Bhi + bo);
            if (TWOTERM) cpa16(nb + OFF_BLO + frow * SA + fkc, Blo + bo);
            asm volatile("cp.async.commit_group;");
        }
        const uint32_t bufb = sb + ((kt & 1) * BUF_STRIDE) * 2;

#pragma unroll
        for (int ks = 0; ks < 2; ks++) {
            const uint32_t kByte = (uint32_t)(ks * 16) * 2;
            uint32_t bh[4][2], bl[4][2];
            const uint32_t bhAddr = bufb + bhOff + kByte;
            ldsm4(bh[0][0], bh[0][1], bh[1][0], bh[1][1], bhAddr);
            ldsm4(bh[2][0], bh[2][1], bh[3][0], bh[3][1], bhAddr + 16 * SA * 2);
            if (TWOTERM) {
                const uint32_t blAddr = bufb + blOff + kByte;
                ldsm4(bl[0][0], bl[0][1], bl[1][0], bl[1][1], blAddr);
                ldsm4(bl[2][0], bl[2][1], bl[3][0], bl[3][1], blAddr + 16 * SA * 2);
            }
            const uint32_t aAddr0 = bufb + aOff + kByte;
#pragma unroll
            for (int mi = 0; mi < 2; mi++) {
                uint32_t a[4];
                ldsm4(a[0], a[1], a[2], a[3], aAddr0 + (uint32_t)(mi * 16 * SA) * 2);
#pragma unroll
                for (int ni = 0; ni < 4; ni++) {
                    mma16816h(acc[mi][ni], a, bh[ni]);
                    if (TWOTERM) mma16816h(acc[mi][ni], a, bl[ni]);
                }
            }
        }
    }

#pragma unroll
    for (int mi = 0; mi < 2; mi++) {
        const int row0 = bm + wm * 32 + mi * 16 + g;
#pragma unroll
        for (int ni = 0; ni < 4; ni++) {
            const int col = bn + wn * 32 + ni * 8 + 2 * t;
            float c0 = acc[mi][ni][0], c1 = acc[mi][ni][1];
            float c2 = acc[mi][ni][2], c3 = acc[mi][ni][3];
            if (BIAS) {
                const float b0 = bias[col], b1 = bias[col + 1];
                c0 += b0; c1 += b1; c2 += b0; c3 += b1;
            }
            if (RELU) {
                c0 = fmaxf(c0, 0.f); c1 = fmaxf(c1, 0.f);
                c2 = fmaxf(c2, 0.f); c3 = fmaxf(c3, 0.f);
            }
#pragma unroll
            for (int rr = 0; rr < 2; rr++) {
                const int row = row0 + rr * 8;
                if (row >= M) continue;
                const float v0 = rr ? c2 : c0;
                const float v1 = rr ? c3 : c1;
                const size_t off = (size_t)row * N + col;
                if (WF32)
                    *reinterpret_cast<float2*>(Cf32 + off) = make_float2(v0, v1);
                if (WF16)
                    *reinterpret_cast<__half2*>(C16 + off) =
                        __float22half2_rn(make_float2(v0, v1));
            }
        }
    }
}

// ---------------- alpha kernels (fp16 p reads) ----------------
__global__ void alpha_kernel(const __half* __restrict__ p, int stride,
                             const float* __restrict__ att,
                             float* __restrict__ out, int N) {
    const int gw = (blockIdx.x * blockDim.x + threadIdx.x) >> 5;
    const int lane = threadIdx.x & 31;
    if (gw >= N * H) return;
    const int n = gw >> 2;
    const int h = gw & 3;
    const __half* pr = p + (size_t)n * stride + h * 64;
    const float* at = att + h * 64;
    float s = __half2float(pr[lane]) * at[lane] +
              __half2float(pr[lane + 32]) * at[lane + 32];
#pragma unroll
    for (int o = 16; o > 0; o >>= 1) s += __shfl_xor_sync(0xffffffffu, s, o);
    if (lane == 0) out[gw] = s;
}

__global__ void alpha5_kernel(const __half* __restrict__ p,
                              const float* __restrict__ a_s0, const float* __restrict__ a_d0,
                              const float* __restrict__ a_s1, const float* __restrict__ a_d1,
                              const float* __restrict__ a_d2,
                              float* __restrict__ as0, float* __restrict__ ad0,
                              float* __restrict__ as1, float* __restrict__ ad1,
                              float* __restrict__ ad2) {
    const int gw = (blockIdx.x * blockDim.x + threadIdx.x) >> 5;
    const int lane = threadIdx.x & 31;
    if (gw >= NT * H) return;
    const int n = gw >> 2;
    const int h = gw & 3;
    const __half* r1 = p + (size_t)n * PW + h * 64;
    const __half* r2 = r1 + 256;
    const __half* r3 = r1 + 512;
    const float x1a = __half2float(r1[lane]), x1b = __half2float(r1[lane + 32]);
    const float x2a = __half2float(r2[lane]), x2b = __half2float(r2[lane + 32]);
    const float x3a = __half2float(r3[lane]), x3b = __half2float(r3[lane + 32]);
    const float* v;
    v = a_s0 + h * 64; float s0 = x1a * v[lane] + x1b * v[lane + 32];
    v = a_d0 + h * 64; float s1 = x1a * v[lane] + x1b * v[lane + 32];
    v = a_s1 + h * 64; float s2 = x2a * v[lane] + x2b * v[lane + 32];
    v = a_d1 + h * 64; float s3 = x2a * v[lane] + x2b * v[lane + 32];
    v = a_d2 + h * 64; float s4 = x3a * v[lane] + x3b * v[lane + 32];
#pragma unroll
    for (int o = 16; o > 0; o >>= 1) {
        s0 += __shfl_xor_sync(0xffffffffu, s0, o);
        s1 += __shfl_xor_sync(0xffffffffu, s1, o);
        s2 += __shfl_xor_sync(0xffffffffu, s2, o);
        s3 += __shfl_xor_sync(0xffffffffu, s3, o);
        s4 += __shfl_xor_sync(0xffffffffu, s4, o);
    }
    if (lane == 0) { as0[gw] = s0; ad0[gw] = s1; as1[gw] = s2; ad1[gw] = s3; ad2[gw] = s4; }
}

// ---------------- fused CSR gather + combine ----------------
__device__ __forceinline__ void acc8_raw(float* acc, float ex, uint4 raw) {
    const __half2* hp = reinterpret_cast<const __half2*>(&raw);
    const float2 f0 = __half22float2(hp[0]);
    const float2 f1 = __half22float2(hp[1]);
    const float2 f2 = __half22float2(hp[2]);
    const float2 f3 = __half22float2(hp[3]);
    acc[0] += ex * f0.x; acc[1] += ex * f0.y;
    acc[2] += ex * f1.x; acc[3] += ex * f1.y;
    acc[4] += ex * f2.x; acc[5] += ex * f2.y;
    acc[6] += ex * f3.x; acc[7] += ex * f3.y;
}
__device__ __forceinline__ float lrelu_exp(float a) {
    a = a > 0.f ? a : 0.2f * a;
    return __expf(a);
}

template <int STRIDE>
__device__ __forceinline__ void gat_pass(
        const int* __restrict__ col, int e0, int e1,
        const float* __restrict__ asrc, float adn, int h,
        const __half* __restrict__ xbase, int k,
        float* acc, float& den) {
    int e = e0;
    for (; e + 4 <= e1; e += 4) {
        const int s0 = __ldg(col + e);
        const int s1 = __ldg(col + e + 1);
        const int s2 = __ldg(col + e + 2);
        const int s3 = __ldg(col + e + 3);
        const float l0 = __ldg(asrc + s0 * 4 + h);
        const float l1 = __ldg(asrc + s1 * 4 + h);
        const float l2 = __ldg(asrc + s2 * 4 + h);
        const float l3 = __ldg(asrc + s3 * 4 + h);
        const uint4 r0 = *reinterpret_cast<const uint4*>(xbase + (size_t)s0 * STRIDE + k);
        const uint4 r1 = *reinterpret_cast<const uint4*>(xbase + (size_t)s1 * STRIDE + k);
        const uint4 r2 = *reinterpret_cast<const uint4*>(xbase + (size_t)s2 * STRIDE + k);
        const uint4 r3 = *reinterpret_cast<const uint4*>(xbase + (size_t)s3 * STRIDE + k);
        const float e0x = lrelu_exp(l0 + adn);
        const float e1x = lrelu_exp(l1 + adn);
        const float e2x = lrelu_exp(l2 + adn);
        const float e3x = lrelu_exp(l3 + adn);
        den += (e0x + e1x) + (e2x + e3x);
        acc8_raw(acc, e0x, r0);
        acc8_raw(acc, e1x, r1);
        acc8_raw(acc, e2x, r2);
        acc8_raw(acc, e3x, r3);
    }
    for (; e < e1; e++) {
        const int s = __ldg(col + e);
        const float ex = lrelu_exp(__ldg(asrc + s * 4 + h) + adn);
        const uint4 r = *reinterpret_cast<const uint4*>(xbase + (size_t)s * STRIDE + k);
        den += ex;
        acc8_raw(acc, ex, r);
    }
}

__global__ void __launch_bounds__(256) gat_gather(
        const int* __restrict__ rowp,
        const int* __restrict__ col0, const int* __restrict__ col1,
        const int* __restrict__ col2,
        const float* __restrict__ as0, const float* __restrict__ ad0,
        const float* __restrict__ as1, const float* __restrict__ ad1,
        const float* __restrict__ as2, const float* __restrict__ ad2,
        const __half* __restrict__ p16, const __half* __restrict__ ps16,
        const float* __restrict__ ht,
        const float* __restrict__ b1, const float* __restrict__ b2,
        const float* __restrict__ b3,
        __half* __restrict__ xb16) {
    const int n = (blockIdx.x * blockDim.x + threadIdx.x) >> 5;
    if (n >= NT) return;
    const int lane = threadIdx.x & 31;
    const int h = lane >> 3;
    const int k = lane * 8;

    const int* rp0 = rowp;
    const int* rp1 = rowp + (NT + 1);
    const int* rp2 = rowp + 2 * (NT + 1);

    float xacc[8];
    float acc[8];

    {
#pragma unroll
        for (int j = 0; j < 8; j++) acc[j] = 0.f;
        float den = 0.f;
        const float adn = ad0[n * 4 + h];
        gat_pass<PW>(col0, rp0[n], rp0[n + 1], as0, adn, h, p16, k, acc, den);
        {
            const float ex = lrelu_exp(as0[n * 4 + h] + adn);
            const uint4 r = *reinterpret_cast<const uint4*>(p16 + (size_t)n * PW + k);
            den += ex;
            acc8_raw(acc, ex, r);
        }
        const float r = 0.25f / fmaxf(den, 1e-16f);
#pragma unroll
        for (int j = 0; j < 8; j++) xacc[j] = r * acc[j];
    }

    {
#pragma unroll
        for (int j = 0; j < 8; j++) acc[j] = 0.f;
        float den = 0.f;
        const float adn = ad1[n * 4 + h];
        gat_pass<PW>(col1, rp1[n], rp1[n + 1], as1, adn, h, p16 + 256, k, acc, den);
        {
            const float ex = lrelu_exp(as1[n * 4 + h] + adn);
            const uint4 r = *reinterpret_cast<const uint4*>(p16 + (size_t)n * PW + 256 + k);
            den += ex;
            acc8_raw(acc, ex, r);
        }
        const float r = 0.25f / fmaxf(den, 1e-16f);
#pragma unroll
        for (int j = 0; j < 8; j++) xacc[j] += r * acc[j];
    }

    {
#pragma unroll
        for (int j = 0; j < 8; j++) acc[j] = 0.f;
        float den = 0.f;
        const float adn = ad2[n * 4 + h];
        gat_pass<HID>(col2, rp2[n], rp2[n + 1], as2, adn, h, ps16, k, acc, den);
        const float r = 0.5f / fmaxf(den, 1e-16f);
#pragma unroll
        for (int j = 0; j < 8; j++) xacc[j] += r * acc[j];
    }

    const float4 b1a = *reinterpret_cast<const float4*>(b1 + k);
    const float4 b1b = *reinterpret_cast<const float4*>(b1 + k + 4);
    const float4 b2a = *reinterpret_cast<const float4*>(b2 + k);
    const float4 b2b = *reinterpret_cast<const float4*>(b2 + k + 4);
    const float4 b3a = *reinterpret_cast<const float4*>(b3 + k);
    const float4 b3b = *reinterpret_cast<const float4*>(b3 + k + 4);
    const float4 h0 = *reinterpret_cast<const float4*>(ht + (size_t)n * HID + k);
    const float4 h1 = *reinterpret_cast<const float4*>(ht + (size_t)n * HID + k + 4);
    float xv[8];
    xv[0] = xacc[0] + 0.25f * (b1a.x + b2a.x) + 0.5f * b3a.x + h0.x;
    xv[1] = xacc[1] + 0.25f * (b1a.y + b2a.y) + 0.5f * b3a.y + h0.y;
    xv[2] = xacc[2] + 0.25f * (b1a.z + b2a.z) + 0.5f * b3a.z + h0.z;
    xv[3] = xacc[3] + 0.25f * (b1a.w + b2a.w) + 0.5f * b3a.w + h0.w;
    xv[4] = xacc[4] + 0.25f * (b1b.x + b2b.x) + 0.5f * b3b.x + h1.x;
    xv[5] = xacc[5] + 0.25f * (b1b.y + b2b.y) + 0.5f * b3b.y + h1.y;
    xv[6] = xacc[6] + 0.25f * (b1b.z + b2b.z) + 0.5f * b3b.z + h1.z;
    xv[7] = xacc[7] + 0.25f * (b1b.w + b2b.w) + 0.5f * b3b.w + h1.w;
    uint4 u;
    __half2* up = reinterpret_cast<__half2*>(&u);
#pragma unroll
    for (int j = 0; j < 4; j++) {
        const float a = fmaxf(xv[2 * j], 0.f);
        const float b = fmaxf(xv[2 * j + 1], 0.f);
        up[j] = __float22half2_rn(make_float2(a, b));
    }
    *reinterpret_cast<uint4*>(xb16 + (size_t)n * HID + k) = u;
}

// ---------------- launch ----------------
extern "C" void kernel_launch(void* const* d_in, const int* in_sizes, int n_in,
                              void* d_out, int out_size) {
    const float* x_target = (const float*)d_in[0];
    const float* x_context = (const float*)d_in[1];
    const int*   ei_tt     = (const int*)d_in[2];
    const int*   ei_ct_src = (const int*)d_in[3];
    const int*   ei_ct_dst = (const int*)d_in[4];
    const float* Wt = (const float*)d_in[5];
    const float* bt = (const float*)d_in[6];
    const float* Wc = (const float*)d_in[7];
    const float* bc = (const float*)d_in[8];
    const float* W_s2d  = (const float*)d_in[9];
    const float* as_s2d = (const float*)d_in[10];
    const float* ad_s2d = (const float*)d_in[11];
    const float* b_s2d  = (const float*)d_in[12];
    const float* W_d2s  = (const float*)d_in[13];
    const float* as_d2s = (const float*)d_in[14];
    const float* ad_d2s = (const float*)d_in[15];
    const float* b_d2s  = (const float*)d_in[16];
    const float* W_ct_src = (const float*)d_in[17];
    const float* W_ct_dst = (const float*)d_in[18];
    const float* as_ct  = (const float*)d_in[19];
    const float* ad_ct  = (const float*)d_in[20];
    const float* b_ct   = (const float*)d_in[21];
    const float* W_out  = (const float*)d_in[22];
    const float* b_out  = (const float*)d_in[23];

    float *ht, *as0, *ad0, *as1, *ad1, *as2, *ad2;
    cudaGetSymbolAddress((void**)&ht,  g_ht);
    cudaGetSymbolAddress((void**)&as0, g_as0);
    cudaGetSymbolAddress((void**)&ad0, g_ad0);
    cudaGetSymbolAddress((void**)&as1, g_as1);
    cudaGetSymbolAddress((void**)&ad1, g_ad1);
    cudaGetSymbolAddress((void**)&as2, g_as2);
    cudaGetSymbolAddress((void**)&ad2, g_ad2);

    __half *p16, *ps16, *xt16, *xc16, *ht16, *hc16, *xb16;
    cudaGetSymbolAddress((void**)&p16,  g_p16);
    cudaGetSymbolAddress((void**)&ps16, g_ps16);
    cudaGetSymbolAddress((void**)&xt16, g_xt16);
    cudaGetSymbolAddress((void**)&xc16, g_xc16);
    cudaGetSymbolAddress((void**)&ht16, g_ht16);
    cudaGetSymbolAddress((void**)&hc16, g_hc16);
    cudaGetSymbolAddress((void**)&xb16, g_xb16);

    int *cnt, *cur, *rowp, *col0, *col1, *col2;
    cudaGetSymbolAddress((void**)&cnt,  g_cnt);
    cudaGetSymbolAddress((void**)&cur,  g_cur);
    cudaGetSymbolAddress((void**)&rowp, g_rowp);
    cudaGetSymbolAddress((void**)&col0, g_col0);
    cudaGetSymbolAddress((void**)&col1, g_col1);
    cudaGetSymbolAddress((void**)&col2, g_col2);

    __half *wt_hi, *wt_lo, *wc_hi, *wc_lo, *w3_hi, *w3_lo, *ws_hi, *ws_lo, *wo_hi, *wo_lo;
    cudaGetSymbolAddress((void**)&wt_hi, g_wt_hi); cudaGetSymbolAddress((void**)&wt_lo, g_wt_lo);
    cudaGetSymbolAddress((void**)&wc_hi, g_wc_hi); cudaGetSymbolAddress((void**)&wc_lo, g_wc_lo);
    cudaGetSymbolAddress((void**)&w3_hi, g_w3_hi); cudaGetSymbolAddress((void**)&w3_lo, g_w3_lo);
    cudaGetSymbolAddress((void**)&ws_hi, g_ws_hi); cudaGetSymbolAddress((void**)&ws_lo, g_ws_lo);
    cudaGetSymbolAddress((void**)&wo_hi, g_wo_hi); cudaGetSymbolAddress((void**)&wo_lo, g_wo_lo);

    // one-time setup (first call is the uncaptured correctness run)
    static cudaStream_t s1 = nullptr, s2 = nullptr;
    static cudaEvent_t eFork = nullptr, eCvt = nullptr, eConv = nullptr;
    static cudaEvent_t eS1 = nullptr, eS2 = nullptr;
    static bool init_done = false;
    if (!init_done) {
        cudaFuncSetAttribute(mma_gemm3<true, true, true, true, true>,
                             cudaFuncAttributeMaxDynamicSharedMemorySize, GEMM_SMEM);
        cudaFuncSetAttribute(mma_gemm3<true, true, false, true, true>,
                             cudaFuncAttributeMaxDynamicSharedMemorySize, GEMM_SMEM);
        cudaFuncSetAttribute(mma_gemm3<false, false, false, true, false>,
                             cudaFuncAttributeMaxDynamicSharedMemorySize, GEMM_SMEM);
        cudaFuncSetAttribute(mma_gemm3<true, false, true, false, false>,
                             cudaFuncAttributeMaxDynamicSharedMemorySize, GEMM_SMEM);
        cudaStreamCreateWithFlags(&s1, cudaStreamNonBlocking);
        cudaStreamCreateWithFlags(&s2, cudaStreamNonBlocking);
        cudaEventCreateWithFlags(&eFork, cudaEventDisableTiming);
        cudaEventCreateWithFlags(&eCvt, cudaEventDisableTiming);
        cudaEventCreateWithFlags(&eConv, cudaEventDisableTiming);
        cudaEventCreateWithFlags(&eS1, cudaEventDisableTiming);
        cudaEventCreateWithFlags(&eS2, cudaEventDisableTiming);
        init_done = true;
    }

    const int* tt_src = ei_tt;
    const int* tt_dst = ei_tt + E_TT;

    const dim3 blk(512);
    const dim3 g_ht_g(HID / 128, (NT + 127) / 128);
    const dim3 g_hc_g(HID / 128, (NC + 127) / 128);
    const dim3 g_p_g(PW / 128, (NT + 127) / 128);

    // ---- fork point ----
    cudaEventRecord(eFork, 0);
    cudaStreamWaitEvent(s1, eFork, 0);
    cudaStreamWaitEvent(s2, eFork, 0);

    // ---- stream s2: activation cvt, then CSR build ----
    {
        const int ncvt = (NT * FT + NC * FC) / 4;
        cvt_all_kernel<<<(ncvt + 255) / 256, 256, 0, s2>>>(x_target, x_context, xt16, xc16);
    }
    cudaEventRecord(eCvt, s2);
    cudaMemsetAsync(cnt, 0, sizeof(int) * 3 * NT, s2);
    count_kernel<<<(E_TT + 255) / 256, 256, 0, s2>>>(tt_src, tt_dst, ei_ct_dst, cnt);
    scan3_kernel<<<3, 1024, 0, s2>>>(cnt, rowp, cur);
    scatter_kernel<<<(E_TT + 255) / 256, 256, 0, s2>>>(tt_src, tt_dst, ei_ct_src,
                                                       ei_ct_dst, cur, col0, col1, col2);
    cudaEventRecord(eS2, s2);

    // ---- stream 0: weight split (concurrent with cvt) ----
    splitW_all_kernel<<<(376832 + 255) / 256, 256>>>(
        Wt, Wc, W_s2d, W_d2s, W_ct_dst, W_ct_src, W_out,
        wt_hi, wt_lo, wc_hi, wc_lo, w3_hi, w3_lo, ws_hi, ws_lo, wo_hi, wo_lo);
    cudaEventRecord(eConv, 0);
    cudaStreamWaitEvent(0, eCvt, 0);

    // ---- stream s1: small context chain (hc -> ps -> alpha(ps)) ----
    cudaStreamWaitEvent(s1, eConv, 0);
    cudaStreamWaitEvent(s1, eCvt, 0);
    mma_gemm3<true, true, false, true, true><<<g_hc_g, blk, GEMM_SMEM, s1>>>(
        xc16, wc_hi, wc_lo, bc, nullptr, hc16, NC, HID, FC);
    mma_gemm3<false, false, false, true, false><<<g_hc_g, blk, GEMM_SMEM, s1>>>(
        hc16, ws_hi, nullptr, nullptr, nullptr, ps16, NC, HID, HID);
    alpha_kernel<<<(NC * H * 32 + 255) / 256, 256, 0, s1>>>(ps16, HID, as_ct, as2, NC);
    cudaEventRecord(eS1, s1);

    // ---- stream 0: big target chain (p-GEMM single-term) ----
    mma_gemm3<true, true, true, true, true><<<g_ht_g, blk, GEMM_SMEM>>>(
        xt16, wt_hi, wt_lo, bt, ht, ht16, NT, HID, FT);
    mma_gemm3<false, false, false, true, false><<<g_p_g, blk, GEMM_SMEM>>>(
        ht16, w3_hi, nullptr, nullptr, nullptr, p16, NT, PW, HID);
    alpha5_kernel<<<(NT * H * 32 + 255) / 256, 256>>>(
        p16, as_s2d, ad_s2d, as_d2s, ad_d2s, ad_ct, as0, ad0, as1, ad1, ad2);

    // ---- join ----
    cudaStreamWaitEvent(0, eS1, 0);
    cudaStreamWaitEvent(0, eS2, 0);

    // ---- fused gather + combine ----
    gat_gather<<<(NT * 32 + 255) / 256, 256>>>(
        rowp, col0, col1, col2, as0, ad0, as1, ad1, as2, ad2,
        p16, ps16, ht, b_s2d, b_d2s, b_ct, xb16);

    // ---- final linear (single-term: xb is fp16-quantized anyway) ----
    mma_gemm3<true, false, true, false, false><<<g_ht_g, blk, GEMM_SMEM>>>(
        xb16, wo_hi, nullptr, b_out, (float*)d_out, nullptr, NT, HID, HID);
}

// round 16
// speedup vs baseline: 1.2477x; 1.0266x over previous
#include <cuda_runtime.h>
#include <cuda_bf16.h>
#include <cuda_fp16.h>
#include <math.h>
#include <stdint.h>

// ---------------- problem constants ----------------
constexpr int NT  = 50000;
constexpr int NC  = 10000;
constexpr int H   = 4;
constexpr int HID = 256;
constexpr int E_TT = 400000;
constexpr int E_CT = 200000;
constexpr int FT = 128;
constexpr int FC = 64;
constexpr int PW = 768;        // p1|p2|pd concat width

// ---------------- device scratch ----------------
__device__ float g_ht[NT * HID];               // fp32 ht for skip connection
__device__ __half g_p16[NT * PW];              // fp16 p (logits + gather)
__device__ __half g_ps16[NC * HID];
__device__ float g_as0[NT * H], g_ad0[NT * H];
__device__ float g_as1[NT * H], g_ad1[NT * H];
__device__ float g_as2[NC * H], g_ad2[NT * H];
// CSR scratch
__device__ int g_cnt[3 * NT];
__device__ int g_cur[3 * NT];
__device__ int g_rowp[3 * (NT + 1)];
__device__ int g_col0[E_TT];
__device__ int g_col1[E_TT];
__device__ int g_col2[E_CT];
// fp16 activations
__device__ __half g_xt16[NT * FT];
__device__ __half g_xc16[NC * FC];
__device__ __half g_ht16[NT * HID];
__device__ __half g_hc16[NC * HID];
__device__ __half g_xb16[NT * HID];
// fp16 hi/lo transposed weights [N, K]
__device__ __half g_wt_hi[HID * FT],  g_wt_lo[HID * FT];
__device__ __half g_wc_hi[HID * FC],  g_wc_lo[HID * FC];
__device__ __half g_w3_hi[PW * HID],  g_w3_lo[PW * HID];   // s2d|d2s|ct_dst
__device__ __half g_ws_hi[HID * HID], g_ws_lo[HID * HID];
__device__ __half g_wo_hi[HID * HID], g_wo_lo[HID * HID];

// ---------------- fused conversion kernels ----------------
__global__ void cvt_all_kernel(const float* __restrict__ xt, const float* __restrict__ xc,
                               __half* __restrict__ xt16, __half* __restrict__ xc16) {
    const int i4 = blockIdx.x * blockDim.x + threadIdx.x;
    constexpr int N1 = NT * FT / 4;
    constexpr int N2 = NC * FC / 4;
    if (i4 >= N1 + N2) return;
    const float* src;
    __half* dst;
    int i;
    if (i4 < N1) { src = xt; dst = xt16; i = i4 * 4; }
    else { src = xc; dst = xc16; i = (i4 - N1) * 4; }
    const float4 v = *reinterpret_cast<const float4*>(src + i);
    *reinterpret_cast<__half2*>(dst + i)     = __float22half2_rn(make_float2(v.x, v.y));
    *reinterpret_cast<__half2*>(dst + i + 2) = __float22half2_rn(make_float2(v.z, v.w));
}

__global__ void splitW_all_kernel(
        const float* __restrict__ Wt, const float* __restrict__ Wc,
        const float* __restrict__ Ws2d, const float* __restrict__ Wd2s,
        const float* __restrict__ Wctd, const float* __restrict__ Wcts,
        const float* __restrict__ Wout,
        __half* __restrict__ wt_hi, __half* __restrict__ wt_lo,
        __half* __restrict__ wc_hi, __half* __restrict__ wc_lo,
        __half* __restrict__ w3_hi, __half* __restrict__ w3_lo,
        __half* __restrict__ ws_hi, __half* __restrict__ ws_lo,
        __half* __restrict__ wo_hi, __half* __restrict__ wo_lo) {
    const int idx = blockIdx.x * blockDim.x + threadIdx.x;
    constexpr int S1 = FT * HID;
    constexpr int S2 = S1 + FC * HID;
    constexpr int S3 = S2 + HID * HID;
    constexpr int S4 = S3 + HID * HID;
    constexpr int S5 = S4 + HID * HID;
    constexpr int S6 = S5 + HID * HID;
    constexpr int S7 = S6 + HID * HID;
    if (idx >= S7) return;
    const float* W; __half *hi, *lo; int K, local, nOff = 0;
    if (idx < S1)      { W = Wt;   hi = wt_hi; lo = wt_lo; K = FT;  local = idx; }
    else if (idx < S2) { W = Wc;   hi = wc_hi; lo = wc_lo; K = FC;  local = idx - S1; }
    else if (idx < S3) { W = Ws2d; hi = w3_hi; lo = w3_lo; K = HID; local = idx - S2; }
    else if (idx < S4) { W = Wd2s; hi = w3_hi; lo = w3_lo; K = HID; local = idx - S3; nOff = 256; }
    else if (idx < S5) { W = Wctd; hi = w3_hi; lo = w3_lo; K = HID; local = idx - S4; nOff = 512; }
    else if (idx < S6) { W = Wcts; hi = ws_hi; lo = ws_lo; K = HID; local = idx - S5; }
    else               { W = Wout; hi = wo_hi; lo = wo_lo; K = HID; local = idx - S6; }
    const int k = local >> 8;
    const int n = local & 255;
    const float v = W[local];
    const __half h = __float2half_rn(v);
    const __half l = __float2half_rn(v - __half2float(h));
    hi[(size_t)(nOff + n) * K + k] = h;
    lo[(size_t)(nOff + n) * K + k] = l;
}

// ---------------- CSR build ----------------
__global__ void count_kernel(const int* __restrict__ tt_src, const int* __restrict__ tt_dst,
                             const int* __restrict__ ct_dst, int* __restrict__ cnt) {
    const int e = blockIdx.x * blockDim.x + threadIdx.x;
    if (e < E_TT) {
        atomicAdd(&cnt[tt_dst[e]], 1);
        atomicAdd(&cnt[NT + tt_src[e]], 1);
    }
    if (e < E_CT) atomicAdd(&cnt[2 * NT + ct_dst[e]], 1);
}

__global__ void __launch_bounds__(1024) scan3_kernel(
        const int* __restrict__ cnt, int* __restrict__ rowp, int* __restrict__ cur) {
    const int a = blockIdx.x;
    const int* c = cnt + a * NT;
    int* rp = rowp + a * (NT + 1);
    int* cu = cur + a * NT;
    __shared__ int warp_tot[32];
    __shared__ int s_carry;
    const int tid = threadIdx.x;
    const int lane = tid & 31, wid = tid >> 5;
    if (tid == 0) s_carry = 0;
    __syncthreads();
    for (int base = 0; base < NT; base += 1024) {
        const int i = base + tid;
        const int v = (i < NT) ? c[i] : 0;
        int x = v;
#pragma unroll
        for (int o = 1; o < 32; o <<= 1) {
            const int y = __shfl_up_sync(~0u, x, o);
            if (lane >= o) x += y;
        }
        if (lane == 31) warp_tot[wid] = x;
        __syncthreads();
        if (wid == 0) {
            int t = warp_tot[lane];
#pragma unroll
            for (int o = 1; o < 32; o <<= 1) {
                const int y = __shfl_up_sync(~0u, t, o);
                if (lane >= o) t += y;
            }
            warp_tot[lane] = t;
        }
        __syncthreads();
        const int carry = s_carry;
        const int woff = (wid > 0) ? warp_tot[wid - 1] : 0;
        const int excl = carry + woff + (x - v);
        if (i < NT) { rp[i] = excl; cu[i] = excl; }
        __syncthreads();
        if (tid == 0) s_carry = carry + warp_tot[31];
        __syncthreads();
    }
    if (tid == 0) rp[NT] = s_carry;
}

__global__ void scatter_kernel(const int* __restrict__ tt_src, const int* __restrict__ tt_dst,
                               const int* __restrict__ ct_src, const int* __restrict__ ct_dst,
                               int* __restrict__ cur,
                               int* __restrict__ col0, int* __restrict__ col1,
                               int* __restrict__ col2) {
    const int e = blockIdx.x * blockDim.x + threadIdx.x;
    if (e < E_TT) {
        const int s = tt_src[e], d = tt_dst[e];
        col0[atomicAdd(&cur[d], 1)] = s;
        col1[atomicAdd(&cur[NT + s], 1)] = d;
    }
    if (e < E_CT) {
        col2[atomicAdd(&cur[2 * NT + ct_dst[e]], 1)] = ct_src[e];
    }
}

// ================= fp16 asymmetric-split tensor-core GEMM (ldmatrix) ========
constexpr int SA = 40;
constexpr int TILE_ARR = 128 * SA;
constexpr int OFF_A   = 0;
constexpr int OFF_BHI = TILE_ARR;
constexpr int OFF_BLO = 2 * TILE_ARR;
constexpr int BUF_STRIDE = 3 * TILE_ARR;
constexpr int GEMM_SMEM = 2 * BUF_STRIDE * 2;       // 61440 B (two-term)
constexpr int GEMM_SMEM_1T = 2 * BUF_STRIDE * 2;    // same layout; single-term just
                                                    // leaves BLO slots unused

__device__ __forceinline__ void cpa16(__half* smem, const __half* gmem) {
    uint32_t sa = (uint32_t)__cvta_generic_to_shared(smem);
    asm volatile("cp.async.ca.shared.global [%0], [%1], 16;" :: "r"(sa), "l"(gmem));
}

__device__ __forceinline__ void mma16816h(float* c, const uint32_t* a, const uint32_t* b) {
    asm volatile(
        "mma.sync.aligned.m16n8k16.row.col.f32.f16.f16.f32 "
        "{%0,%1,%2,%3}, {%4,%5,%6,%7}, {%8,%9}, {%0,%1,%2,%3};"
        : "+f"(c[0]), "+f"(c[1]), "+f"(c[2]), "+f"(c[3])
        : "r"(a[0]), "r"(a[1]), "r"(a[2]), "r"(a[3]), "r"(b[0]), "r"(b[1]));
}

__device__ __forceinline__ void ldsm4(uint32_t& r0, uint32_t& r1, uint32_t& r2,
                                      uint32_t& r3, uint32_t addr) {
    asm volatile("ldmatrix.sync.aligned.m8n8.x4.shared.b16 {%0,%1,%2,%3}, [%4];"
                 : "=r"(r0), "=r"(r1), "=r"(r2), "=r"(r3) : "r"(addr));
}

// TWOTERM: B = Bhi + Blo (2 MMA terms); else Bhi only (1 term).
template <bool BIAS, bool RELU, bool WF32, bool WF16, bool TWOTERM>
__global__ void __launch_bounds__(512, 2) mma_gemm3(
        const __half* __restrict__ A,
        const __half* __restrict__ Bhi, const __half* __restrict__ Blo,
        const float* __restrict__ bias,
        float* __restrict__ Cf32, __half* __restrict__ C16,
        int M, int N, int K) {
    extern __shared__ __align__(16) char dynsmem[];
    __half* sm = reinterpret_cast<__half*>(dynsmem);
    const uint32_t sb = (uint32_t)__cvta_generic_to_shared(sm);

    const int tid = threadIdx.x;
    const int bm = blockIdx.y * 128;
    const int bn = blockIdx.x * 128;
    const int wid = tid >> 5;
    const int lane = tid & 31;
    const int wm = wid >> 2;
    const int wn = wid & 3;
    const int g = lane >> 2;
    const int t = lane & 3;

    const int frow = tid >> 2;
    const int fkc  = (tid & 3) * 8;
    int garow = bm + frow; if (garow >= M) garow = M - 1;
    const int gbrow = bn + frow;

    const int aRow = wm * 32 + (lane & 7) + ((lane >> 3) & 1) * 8;
    const int aK   = ((lane >> 4) & 1) * 8;
    const int bRow = wn * 32 + (lane & 7) + ((lane >> 4) & 1) * 8;
    const int bK   = ((lane >> 3) & 1) * 8;
    const uint32_t aOff  = (uint32_t)(OFF_A   + aRow * SA + aK) * 2;
    const uint32_t bhOff = (uint32_t)(OFF_BHI + bRow * SA + bK) * 2;
    const uint32_t blOff = (uint32_t)(OFF_BLO + bRow * SA + bK) * 2;

    float acc[2][4][4];
#pragma unroll
    for (int mi = 0; mi < 2; mi++)
#pragma unroll
        for (int ni = 0; ni < 4; ni++)
#pragma unroll
            for (int r = 0; r < 4; r++) acc[mi][ni][r] = 0.f;

    const int KT = K >> 5;
    {
        const size_t ao = (size_t)garow * K + fkc;
        const size_t bo = (size_t)gbrow * K + fkc;
        __half* b0 = sm;
        cpa16(b0 + OFF_A   + frow * SA + fkc, A + ao);
        cpa16(b0 + OFF_BHI + frow * SA + fkc, Bhi + bo);
        if (TWOTERM) cpa16(b0 + OFF_BLO + frow * SA + fkc, Blo + bo);
        asm volatile("cp.async.commit_group;");
    }

    for (int kt = 0; kt < KT; kt++) {
        asm volatile("cp.async.wait_group 0;");
        __syncthreads();
        if (kt + 1 < KT) {
            const int k0 = (kt + 1) << 5;
            const size_t ao = (size_t)garow * K + k0 + fkc;
            const size_t bo = (size_t)gbrow * K + k0 + fkc;
            __half* nb = sm + ((kt + 1) & 1) * BUF_STRIDE;
            cpa16(nb + OFF_A   + frow * SA + fkc, A + ao);
            cpa16(nb + OFF_BHI + frow * SA + fkc, Bhi + bo);
            if (TWOTERM) cpa16(nb + OFF_BLO + frow * SA + fkc, Blo + bo);
            asm volatile("cp.async.commit_group;");
        }
        const uint32_t bufb = sb + ((kt & 1) * BUF_STRIDE) * 2;

#pragma unroll
        for (int ks = 0; ks < 2; ks++) {
            const uint32_t kByte = (uint32_t)(ks * 16) * 2;
            uint32_t bh[4][2], bl[4][2];
            const uint32_t bhAddr = bufb + bhOff + kByte;
            ldsm4(bh[0][0], bh[0][1], bh[1][0], bh[1][1], bhAddr);
            ldsm4(bh[2][0], bh[2][1], bh[3][0], bh[3][1], bhAddr + 16 * SA * 2);
            if (TWOTERM) {
                const uint32_t blAddr = bufb + blOff + kByte;
                ldsm4(bl[0][0], bl[0][1], bl[1][0], bl[1][1], blAddr);
                ldsm4(bl[2][0], bl[2][1], bl[3][0], bl[3][1], blAddr + 16 * SA * 2);
            }
            const uint32_t aAddr0 = bufb + aOff + kByte;
#pragma unroll
            for (int mi = 0; mi < 2; mi++) {
                uint32_t a[4];
                ldsm4(a[0], a[1], a[2], a[3], aAddr0 + (uint32_t)(mi * 16 * SA) * 2);
#pragma unroll
                for (int ni = 0; ni < 4; ni++) {
                    mma16816h(acc[mi][ni], a, bh[ni]);
                    if (TWOTERM) mma16816h(acc[mi][ni], a, bl[ni]);
                }
            }
        }
    }

#pragma unroll
    for (int mi = 0; mi < 2; mi++) {
        const int row0 = bm + wm * 32 + mi * 16 + g;
#pragma unroll
        for (int ni = 0; ni < 4; ni++) {
            const int col = bn + wn * 32 + ni * 8 + 2 * t;
            float c0 = acc[mi][ni][0], c1 = acc[mi][ni][1];
            float c2 = acc[mi][ni][2], c3 = acc[mi][ni][3];
            if (BIAS) {
                const float b0 = bias[col], b1 = bias[col + 1];
                c0 += b0; c1 += b1; c2 += b0; c3 += b1;
            }
            if (RELU) {
                c0 = fmaxf(c0, 0.f); c1 = fmaxf(c1, 0.f);
                c2 = fmaxf(c2, 0.f); c3 = fmaxf(c3, 0.f);
            }
#pragma unroll
            for (int rr = 0; rr < 2; rr++) {
                const int row = row0 + rr * 8;
                if (row >= M) continue;
                const float v0 = rr ? c2 : c0;
                const float v1 = rr ? c3 : c1;
                const size_t off = (size_t)row * N + col;
                if (WF32)
                    *reinterpret_cast<float2*>(Cf32 + off) = make_float2(v0, v1);
                if (WF16)
                    *reinterpret_cast<__half2*>(C16 + off) =
                        __float22half2_rn(make_float2(v0, v1));
            }
        }
    }
}

// ---------------- alpha kernels (fp16 p reads) ----------------
__global__ void alpha_kernel(const __half* __restrict__ p, int stride,
                             const float* __restrict__ att,
                             float* __restrict__ out, int N) {
    const int gw = (blockIdx.x * blockDim.x + threadIdx.x) >> 5;
    const int lane = threadIdx.x & 31;
    if (gw >= N * H) return;
    const int n = gw >> 2;
    const int h = gw & 3;
    const __half* pr = p + (size_t)n * stride + h * 64;
    const float* at = att + h * 64;
    float s = __half2float(pr[lane]) * at[lane] +
              __half2float(pr[lane + 32]) * at[lane + 32];
#pragma unroll
    for (int o = 16; o > 0; o >>= 1) s += __shfl_xor_sync(0xffffffffu, s, o);
    if (lane == 0) out[gw] = s;
}

__global__ void alpha5_kernel(const __half* __restrict__ p,
                              const float* __restrict__ a_s0, const float* __restrict__ a_d0,
                              const float* __restrict__ a_s1, const float* __restrict__ a_d1,
                              const float* __restrict__ a_d2,
                              float* __restrict__ as0, float* __restrict__ ad0,
                              float* __restrict__ as1, float* __restrict__ ad1,
                              float* __restrict__ ad2) {
    const int gw = (blockIdx.x * blockDim.x + threadIdx.x) >> 5;
    const int lane = threadIdx.x & 31;
    if (gw >= NT * H) return;
    const int n = gw >> 2;
    const int h = gw & 3;
    const __half* r1 = p + (size_t)n * PW + h * 64;
    const __half* r2 = r1 + 256;
    const __half* r3 = r1 + 512;
    const float x1a = __half2float(r1[lane]), x1b = __half2float(r1[lane + 32]);
    const float x2a = __half2float(r2[lane]), x2b = __half2float(r2[lane + 32]);
    const float x3a = __half2float(r3[lane]), x3b = __half2float(r3[lane + 32]);
    const float* v;
    v = a_s0 + h * 64; float s0 = x1a * v[lane] + x1b * v[lane + 32];
    v = a_d0 + h * 64; float s1 = x1a * v[lane] + x1b * v[lane + 32];
    v = a_s1 + h * 64; float s2 = x2a * v[lane] + x2b * v[lane + 32];
    v = a_d1 + h * 64; float s3 = x2a * v[lane] + x2b * v[lane + 32];
    v = a_d2 + h * 64; float s4 = x3a * v[lane] + x3b * v[lane + 32];
#pragma unroll
    for (int o = 16; o > 0; o >>= 1) {
        s0 += __shfl_xor_sync(0xffffffffu, s0, o);
        s1 += __shfl_xor_sync(0xffffffffu, s1, o);
        s2 += __shfl_xor_sync(0xffffffffu, s2, o);
        s3 += __shfl_xor_sync(0xffffffffu, s3, o);
        s4 += __shfl_xor_sync(0xffffffffu, s4, o);
    }
    if (lane == 0) { as0[gw] = s0; ad0[gw] = s1; as1[gw] = s2; ad1[gw] = s3; ad2[gw] = s4; }
}

// ---------------- fused CSR gather + combine ----------------
__device__ __forceinline__ void acc8_raw(float* acc, float ex, uint4 raw) {
    const __half2* hp = reinterpret_cast<const __half2*>(&raw);
    const float2 f0 = __half22float2(hp[0]);
    const float2 f1 = __half22float2(hp[1]);
    const float2 f2 = __half22float2(hp[2]);
    const float2 f3 = __half22float2(hp[3]);
    acc[0] += ex * f0.x; acc[1] += ex * f0.y;
    acc[2] += ex * f1.x; acc[3] += ex * f1.y;
    acc[4] += ex * f2.x; acc[5] += ex * f2.y;
    acc[6] += ex * f3.x; acc[7] += ex * f3.y;
}
__device__ __forceinline__ float lrelu_exp(float a) {
    a = a > 0.f ? a : 0.2f * a;
    return __expf(a);
}

template <int STRIDE>
__device__ __forceinline__ void gat_pass(
        const int* __restrict__ col, int e0, int e1,
        const float* __restrict__ asrc, float adn, int h,
        const __half* __restrict__ xbase, int k,
        float* acc, float& den) {
    int e = e0;
    for (; e + 4 <= e1; e += 4) {
        const int s0 = __ldg(col + e);
        const int s1 = __ldg(col + e + 1);
        const int s2 = __ldg(col + e + 2);
        const int s3 = __ldg(col + e + 3);
        const float l0 = __ldg(asrc + s0 * 4 + h);
        const float l1 = __ldg(asrc + s1 * 4 + h);
        const float l2 = __ldg(asrc + s2 * 4 + h);
        const float l3 = __ldg(asrc + s3 * 4 + h);
        const uint4 r0 = *reinterpret_cast<const uint4*>(xbase + (size_t)s0 * STRIDE + k);
        const uint4 r1 = *reinterpret_cast<const uint4*>(xbase + (size_t)s1 * STRIDE + k);
        const uint4 r2 = *reinterpret_cast<const uint4*>(xbase + (size_t)s2 * STRIDE + k);
        const uint4 r3 = *reinterpret_cast<const uint4*>(xbase + (size_t)s3 * STRIDE + k);
        const float e0x = lrelu_exp(l0 + adn);
        const float e1x = lrelu_exp(l1 + adn);
        const float e2x = lrelu_exp(l2 + adn);
        const float e3x = lrelu_exp(l3 + adn);
        den += (e0x + e1x) + (e2x + e3x);
        acc8_raw(acc, e0x, r0);
        acc8_raw(acc, e1x, r1);
        acc8_raw(acc, e2x, r2);
        acc8_raw(acc, e3x, r3);
    }
    for (; e < e1; e++) {
        const int s = __ldg(col + e);
        const float ex = lrelu_exp(__ldg(asrc + s * 4 + h) + adn);
        const uint4 r = *reinterpret_cast<const uint4*>(xbase + (size_t)s * STRIDE + k);
        den += ex;
        acc8_raw(acc, ex, r);
    }
}

__global__ void __launch_bounds__(256) gat_gather(
        const int* __restrict__ rowp,
        const int* __restrict__ col0, const int* __restrict__ col1,
        const int* __restrict__ col2,
        const float* __restrict__ as0, const float* __restrict__ ad0,
        const float* __restrict__ as1, const float* __restrict__ ad1,
        const float* __restrict__ as2, const float* __restrict__ ad2,
        const __half* __restrict__ p16, const __half* __restrict__ ps16,
        const float* __restrict__ ht,
        const float* __restrict__ b1, const float* __restrict__ b2,
        const float* __restrict__ b3,
        __half* __restrict__ xb16) {
    const int n = (blockIdx.x * blockDim.x + threadIdx.x) >> 5;
    if (n >= NT) return;
    const int lane = threadIdx.x & 31;
    const int h = lane >> 3;
    const int k = lane * 8;

    const int* rp0 = rowp;
    const int* rp1 = rowp + (NT + 1);
    const int* rp2 = rowp + 2 * (NT + 1);

    float xacc[8];
    float acc[8];

    {
#pragma unroll
        for (int j = 0; j < 8; j++) acc[j] = 0.f;
        float den = 0.f;
        const float adn = ad0[n * 4 + h];
        gat_pass<PW>(col0, rp0[n], rp0[n + 1], as0, adn, h, p16, k, acc, den);
        {
            const float ex = lrelu_exp(as0[n * 4 + h] + adn);
            const uint4 r = *reinterpret_cast<const uint4*>(p16 + (size_t)n * PW + k);
            den += ex;
            acc8_raw(acc, ex, r);
        }
        const float r = 0.25f / fmaxf(den, 1e-16f);
#pragma unroll
        for (int j = 0; j < 8; j++) xacc[j] = r * acc[j];
    }

    {
#pragma unroll
        for (int j = 0; j < 8; j++) acc[j] = 0.f;
        float den = 0.f;
        const float adn = ad1[n * 4 + h];
        gat_pass<PW>(col1, rp1[n], rp1[n + 1], as1, adn, h, p16 + 256, k, acc, den);
        {
            const float ex = lrelu_exp(as1[n * 4 + h] + adn);
            const uint4 r = *reinterpret_cast<const uint4*>(p16 + (size_t)n * PW + 256 + k);
            den += ex;
            acc8_raw(acc, ex, r);
        }
        const float r = 0.25f / fmaxf(den, 1e-16f);
#pragma unroll
        for (int j = 0; j < 8; j++) xacc[j] += r * acc[j];
    }

    {
#pragma unroll
        for (int j = 0; j < 8; j++) acc[j] = 0.f;
        float den = 0.f;
        const float adn = ad2[n * 4 + h];
        gat_pass<HID>(col2, rp2[n], rp2[n + 1], as2, adn, h, ps16, k, acc, den);
        const float r = 0.5f / fmaxf(den, 1e-16f);
#pragma unroll
        for (int j = 0; j < 8; j++) xacc[j] += r * acc[j];
    }

    const float4 b1a = *reinterpret_cast<const float4*>(b1 + k);
    const float4 b1b = *reinterpret_cast<const float4*>(b1 + k + 4);
    const float4 b2a = *reinterpret_cast<const float4*>(b2 + k);
    const float4 b2b = *reinterpret_cast<const float4*>(b2 + k + 4);
    const float4 b3a = *reinterpret_cast<const float4*>(b3 + k);
    const float4 b3b = *reinterpret_cast<const float4*>(b3 + k + 4);
    const float4 h0 = *reinterpret_cast<const float4*>(ht + (size_t)n * HID + k);
    const float4 h1 = *reinterpret_cast<const float4*>(ht + (size_t)n * HID + k + 4);
    float xv[8];
    xv[0] = xacc[0] + 0.25f * (b1a.x + b2a.x) + 0.5f * b3a.x + h0.x;
    xv[1] = xacc[1] + 0.25f * (b1a.y + b2a.y) + 0.5f * b3a.y + h0.y;
    xv[2] = xacc[2] + 0.25f * (b1a.z + b2a.z) + 0.5f * b3a.z + h0.z;
    xv[3] = xacc[3] + 0.25f * (b1a.w + b2a.w) + 0.5f * b3a.w + h0.w;
    xv[4] = xacc[4] + 0.25f * (b1b.x + b2b.x) + 0.5f * b3b.x + h1.x;
    xv[5] = xacc[5] + 0.25f * (b1b.y + b2b.y) + 0.5f * b3b.y + h1.y;
    xv[6] = xacc[6] + 0.25f * (b1b.z + b2b.z) + 0.5f * b3b.z + h1.z;
    xv[7] = xacc[7] + 0.25f * (b1b.w + b2b.w) + 0.5f * b3b.w + h1.w;
    uint4 u;
    __half2* up = reinterpret_cast<__half2*>(&u);
#pragma unroll
    for (int j = 0; j < 4; j++) {
        const float a = fmaxf(xv[2 * j], 0.f);
        const float b = fmaxf(xv[2 * j + 1], 0.f);
        up[j] = __float22half2_rn(make_float2(a, b));
    }
    *reinterpret_cast<uint4*>(xb16 + (size_t)n * HID + k) = u;
}

// ---------------- launch ----------------
extern "C" void kernel_launch(void* const* d_in, const int* in_sizes, int n_in,
                              void* d_out, int out_size) {
    const float* x_target = (const float*)d_in[0];
    const float* x_context = (const float*)d_in[1];
    const int*   ei_tt     = (const int*)d_in[2];
    const int*   ei_ct_src = (const int*)d_in[3];
    const int*   ei_ct_dst = (const int*)d_in[4];
    const float* Wt = (const float*)d_in[5];
    const float* bt = (const float*)d_in[6];
    const float* Wc = (const float*)d_in[7];
    const float* bc = (const float*)d_in[8];
    const float* W_s2d  = (const float*)d_in[9];
    const float* as_s2d = (const float*)d_in[10];
    const float* ad_s2d = (const float*)d_in[11];
    const float* b_s2d  = (const float*)d_in[12];
    const float* W_d2s  = (const float*)d_in[13];
    const float* as_d2s = (const float*)d_in[14];
    const float* ad_d2s = (const float*)d_in[15];
    const float* b_d2s  = (const float*)d_in[16];
    const float* W_ct_src = (const float*)d_in[17];
    const float* W_ct_dst = (const float*)d_in[18];
    const float* as_ct  = (const float*)d_in[19];
    const float* ad_ct  = (const float*)d_in[20];
    const float* b_ct   = (const float*)d_in[21];
    const float* W_out  = (const float*)d_in[22];
    const float* b_out  = (const float*)d_in[23];

    float *ht, *as0, *ad0, *as1, *ad1, *as2, *ad2;
    cudaGetSymbolAddress((void**)&ht,  g_ht);
    cudaGetSymbolAddress((void**)&as0, g_as0);
    cudaGetSymbolAddress((void**)&ad0, g_ad0);
    cudaGetSymbolAddress((void**)&as1, g_as1);
    cudaGetSymbolAddress((void**)&ad1, g_ad1);
    cudaGetSymbolAddress((void**)&as2, g_as2);
    cudaGetSymbolAddress((void**)&ad2, g_ad2);

    __half *p16, *ps16, *xt16, *xc16, *ht16, *hc16, *xb16;
    cudaGetSymbolAddress((void**)&p16,  g_p16);
    cudaGetSymbolAddress((void**)&ps16, g_ps16);
    cudaGetSymbolAddress((void**)&xt16, g_xt16);
    cudaGetSymbolAddress((void**)&xc16, g_xc16);
    cudaGetSymbolAddress((void**)&ht16, g_ht16);
    cudaGetSymbolAddress((void**)&hc16, g_hc16);
    cudaGetSymbolAddress((void**)&xb16, g_xb16);

    int *cnt, *cur, *rowp, *col0, *col1, *col2;
    cudaGetSymbolAddress((void**)&cnt,  g_cnt);
    cudaGetSymbolAddress((void**)&cur,  g_cur);
    cudaGetSymbolAddress((void**)&rowp, g_rowp);
    cudaGetSymbolAddress((void**)&col0, g_col0);
    cudaGetSymbolAddress((void**)&col1, g_col1);
    cudaGetSymbolAddress((void**)&col2, g_col2);

    __half *wt_hi, *wt_lo, *wc_hi, *wc_lo, *w3_hi, *w3_lo, *ws_hi, *ws_lo, *wo_hi, *wo_lo;
    cudaGetSymbolAddress((void**)&wt_hi, g_wt_hi); cudaGetSymbolAddress((void**)&wt_lo, g_wt_lo);
    cudaGetSymbolAddress((void**)&wc_hi, g_wc_hi); cudaGetSymbolAddress((void**)&wc_lo, g_wc_lo);
    cudaGetSymbolAddress((void**)&w3_hi, g_w3_hi); cudaGetSymbolAddress((void**)&w3_lo, g_w3_lo);
    cudaGetSymbolAddress((void**)&ws_hi, g_ws_hi); cudaGetSymbolAddress((void**)&ws_lo, g_ws_lo);
    cudaGetSymbolAddress((void**)&wo_hi, g_wo_hi); cudaGetSymbolAddress((void**)&wo_lo, g_wo_lo);

    // one-time setup (first call is the uncaptured correctness run)
    static cudaStream_t s1 = nullptr, s2 = nullptr;
    static cudaEvent_t eFork = nullptr, eCvt = nullptr, eConv = nullptr;
    static cudaEvent_t eS1 = nullptr, eS2 = nullptr;
    static bool init_done = false;
    if (!init_done) {
        cudaFuncSetAttribute(mma_gemm3<true, true, true, true, false>,
                             cudaFuncAttributeMaxDynamicSharedMemorySize, GEMM_SMEM);
        cudaFuncSetAttribute(mma_gemm3<true, true, false, true, true>,
                             cudaFuncAttributeMaxDynamicSharedMemorySize, GEMM_SMEM);
        cudaFuncSetAttribute(mma_gemm3<false, false, false, true, false>,
                             cudaFuncAttributeMaxDynamicSharedMemorySize, GEMM_SMEM);
        cudaFuncSetAttribute(mma_gemm3<true, false, true, false, false>,
                             cudaFuncAttributeMaxDynamicSharedMemorySize, GEMM_SMEM);
        cudaStreamCreateWithFlags(&s1, cudaStreamNonBlocking);
        cudaStreamCreateWithFlags(&s2, cudaStreamNonBlocking);
        cudaEventCreateWithFlags(&eFork, cudaEventDisableTiming);
        cudaEventCreateWithFlags(&eCvt, cudaEventDisableTiming);
        cudaEventCreateWithFlags(&eConv, cudaEventDisableTiming);
        cudaEventCreateWithFlags(&eS1, cudaEventDisableTiming);
        cudaEventCreateWithFlags(&eS2, cudaEventDisableTiming);
        init_done = true;
    }

    const int* tt_src = ei_tt;
    const int* tt_dst = ei_tt + E_TT;

    const dim3 blk(512);
    const dim3 g_ht_g(HID / 128, (NT + 127) / 128);
    const dim3 g_hc_g(HID / 128, (NC + 127) / 128);
    const dim3 g_p_g(PW / 128, (NT + 127) / 128);

    // ---- fork point ----
    cudaEventRecord(eFork, 0);
    cudaStreamWaitEvent(s1, eFork, 0);
    cudaStreamWaitEvent(s2, eFork, 0);

    // ---- stream s2: activation cvt, then CSR build ----
    {
        const int ncvt = (NT * FT + NC * FC) / 4;
        cvt_all_kernel<<<(ncvt + 255) / 256, 256, 0, s2>>>(x_target, x_context, xt16, xc16);
    }
    cudaEventRecord(eCvt, s2);
    cudaMemsetAsync(cnt, 0, sizeof(int) * 3 * NT, s2);
    count_kernel<<<(E_TT + 255) / 256, 256, 0, s2>>>(tt_src, tt_dst, ei_ct_dst, cnt);
    scan3_kernel<<<3, 1024, 0, s2>>>(cnt, rowp, cur);
    scatter_kernel<<<(E_TT + 255) / 256, 256, 0, s2>>>(tt_src, tt_dst, ei_ct_src,
                                                       ei_ct_dst, cur, col0, col1, col2);
    cudaEventRecord(eS2, s2);

    // ---- stream 0: weight split (concurrent with cvt) ----
    splitW_all_kernel<<<(376832 + 255) / 256, 256>>>(
        Wt, Wc, W_s2d, W_d2s, W_ct_dst, W_ct_src, W_out,
        wt_hi, wt_lo, wc_hi, wc_lo, w3_hi, w3_lo, ws_hi, ws_lo, wo_hi, wo_lo);
    cudaEventRecord(eConv, 0);
    cudaStreamWaitEvent(0, eCvt, 0);

    // ---- stream s1: small context chain (hc -> ps -> alpha(ps)) ----
    cudaStreamWaitEvent(s1, eConv, 0);
    cudaStreamWaitEvent(s1, eCvt, 0);
    mma_gemm3<true, true, false, true, true><<<g_hc_g, blk, GEMM_SMEM, s1>>>(
        xc16, wc_hi, wc_lo, bc, nullptr, hc16, NC, HID, FC);
    mma_gemm3<false, false, false, true, false><<<g_hc_g, blk, GEMM_SMEM, s1>>>(
        hc16, ws_hi, nullptr, nullptr, nullptr, ps16, NC, HID, HID);
    alpha_kernel<<<(NC * H * 32 + 255) / 256, 256, 0, s1>>>(ps16, HID, as_ct, as2, NC);
    cudaEventRecord(eS1, s1);

    // ---- stream 0: big target chain (ht and p both single-term) ----
    mma_gemm3<true, true, true, true, false><<<g_ht_g, blk, GEMM_SMEM>>>(
        xt16, wt_hi, nullptr, bt, ht, ht16, NT, HID, FT);
    mma_gemm3<false, false, false, true, false><<<g_p_g, blk, GEMM_SMEM>>>(
        ht16, w3_hi, nullptr, nullptr, nullptr, p16, NT, PW, HID);
    alpha5_kernel<<<(NT * H * 32 + 255) / 256, 256>>>(
        p16, as_s2d, ad_s2d, as_d2s, ad_d2s, ad_ct, as0, ad0, as1, ad1, ad2);

    // ---- join ----
    cudaStreamWaitEvent(0, eS1, 0);
    cudaStreamWaitEvent(0, eS2, 0);

    // ---- fused gather + combine ----
    gat_gather<<<(NT * 32 + 255) / 256, 256>>>(
        rowp, col0, col1, col2, as0, ad0, as1, ad1, as2, ad2,
        p16, ps16, ht, b_s2d, b_d2s, b_ct, xb16);

    // ---- final linear (single-term: xb is fp16-quantized anyway) ----
    mma_gemm3<true, false, true, false, false><<<g_ht_g, blk, GEMM_SMEM>>>(
        xb16, wo_hi, nullptr, b_out, (float*)d_out, nullptr, NT, HID, HID);
}